// round 14
// baseline (speedup 1.0000x reference)
#include <cuda_runtime.h>

#define NRAYS 16384
#define NSTEPS 100
#define STH 5e-5f

// ---------------- device scratch (no allocations allowed) ----------------
__device__ float g_c1[64];
__device__ float g_acc_s[NRAYS];
__device__ float g_acc_e[NRAYS];
__device__ float g_next_s[NRAYS];
__device__ float g_next_e[NRAYS];
__device__ unsigned char g_unfin[NRAYS];         // bit0 unfin_s, bit1 unfin_e, bit2 no_int
__device__ float g_sdfval[NSTEPS * NRAYS];       // sample-major: [s*NRAYS + r]
__device__ int g_mask_mode;                      // 0=bytes, 1=int32 words, 2=float32 words
__device__ int g_count;                          // number of sampler rays
__device__ int g_list[NRAYS];                    // compacted sampler-ray indices
__device__ int g_tcnt[11];                       // active-ray count per trace iteration
__device__ int g_tlist[11][NRAYS];               // active-ray lists per trace iteration
__device__ int g_scnt;                           // secant ray count
__device__ int g_slist[NRAYS];                   // secant ray indices
__device__ float g_szl[NRAYS], g_szh[NRAYS], g_ssl[NRAYS], g_ssh[NRAYS];

// Exact XLA-style elementwise ops: separate RN mul/add (no FMA contraction).
#define MUL(a, b) __fmul_rn((a), (b))
#define ADD(a, b) __fadd_rn((a), (b))
#define SUB(a, b) __fsub_rn((a), (b))

// Packed f32x2 ops (sm_100+). Each half rounds exactly like scalar IEEE FMA.
#define FMA2(acc, a, b) \
    asm("fma.rn.f32x2 %0, %1, %2, %0;" : "+l"(acc) : "l"(a), "l"(b))
#define PACK2(d, s) \
    asm("mov.b64 %0, {%1, %1};" : "=l"(d) : "r"(s))
#define UNPACK2(lo, hi, v) \
    asm("mov.b64 {%0, %1}, %2;" : "=r"(lo), "=r"(hi) : "l"(v))

// ---------------- shared weight cache ----------------
struct __align__(16) SdfShared {
    float4 W1p[64];     // {W1x[k], W1y[k], W1z[k], c1[k]}
    float b2[64];
    float W3[64];
    float W2[64 * 64];  // row-major [k][j]
    float cam[3];
    float b3;
};

__device__ __forceinline__ float softplusf(float x) {
    return ADD(fmaxf(x, 0.0f), __logf(__fadd_rn(1.0f, __expf(-fabsf(x)))));
}

__device__ __forceinline__ void load_shared(SdfShared* sh, const float* W1, const float* W2,
                                            const float* b2, const float* W3, const float* b3,
                                            const float* cam) {
    int t = threadIdx.x, nt = blockDim.x;
    for (int i = t; i < 64 * 64; i += nt) sh->W2[i] = W2[i];
    for (int i = t; i < 64; i += nt) {
        sh->W1p[i] = make_float4(W1[i], W1[64 + i], W1[128 + i], g_c1[i]);
        sh->b2[i] = b2[i];
        sh->W3[i] = W3[i];
    }
    if (t == 0) {
        sh->b3 = b3[0];
        sh->cam[0] = cam[0]; sh->cam[1] = cam[1]; sh->cam[2] = cam[2];
    }
    __syncthreads();
}

// Single-sample SDF eval (secant). Layer-2 in packed f32x2 FMA.
__device__ __noinline__ float sdf_eval(const SdfShared* __restrict__ sh,
                                       float x, float y, float z) {
    unsigned long long acc2[32];
#pragma unroll
    for (int m = 0; m < 32; ++m) acc2[m] = 0ull;
#pragma unroll 8
    for (int k = 0; k < 64; ++k) {
        float4 w1 = sh->W1p[k];
        float pre = w1.w;
        pre = fmaf(x, w1.x, pre);
        pre = fmaf(y, w1.y, pre);
        pre = fmaf(z, w1.z, pre);
        float hk = softplusf(pre);
        unsigned long long hk2;
        PACK2(hk2, __float_as_uint(hk));
        const ulonglong2* wrow = (const ulonglong2*)(sh->W2) + k * 16;
#pragma unroll
        for (int j = 0; j < 16; ++j) {
            ulonglong2 wv = wrow[j];
            FMA2(acc2[2 * j + 0], hk2, wv.x);
            FMA2(acc2[2 * j + 1], hk2, wv.y);
        }
    }
    float d0 = 0.f, d1 = 0.f, d2 = 0.f, d3 = 0.f;
#pragma unroll
    for (int m = 0; m < 32; m += 2) {
        unsigned l0, h0, l1, h1;
        UNPACK2(l0, h0, acc2[m]);
        UNPACK2(l1, h1, acc2[m + 1]);
        int j = 2 * m;
        d0 = fmaf(softplusf(ADD(__uint_as_float(l0), sh->b2[j + 0])), sh->W3[j + 0], d0);
        d1 = fmaf(softplusf(ADD(__uint_as_float(h0), sh->b2[j + 1])), sh->W3[j + 1], d1);
        d2 = fmaf(softplusf(ADD(__uint_as_float(l1), sh->b2[j + 2])), sh->W3[j + 2], d2);
        d3 = fmaf(softplusf(ADD(__uint_as_float(h1), sh->b2[j + 3])), sh->W3[j + 3], d3);
    }
    float delta = ADD(((d0 + d1) + (d2 + d3)), sh->b3);
    float r2 = ADD(ADD(ADD(MUL(x, x), MUL(y, y)), MUL(z, z)), 1e-12f);
    return ADD(SUB(sqrtf(r2), 0.5f), MUL(0.05f, tanhf(delta)));
}

// Two-sample SDF eval: amortizes weight loads, doubles per-thread ILP.
// Per-point math identical to sdf_eval (bit-identical results).
__device__ __noinline__ void sdf_eval2(const SdfShared* __restrict__ sh,
                                       float xa, float ya, float za,
                                       float xb, float yb, float zb,
                                       float* __restrict__ oa, float* __restrict__ ob) {
    unsigned long long accA[32], accB[32];
#pragma unroll
    for (int m = 0; m < 32; ++m) { accA[m] = 0ull; accB[m] = 0ull; }
#pragma unroll 2
    for (int k = 0; k < 64; ++k) {
        float4 w1 = sh->W1p[k];
        float preA = w1.w, preB = w1.w;
        preA = fmaf(xa, w1.x, preA);  preB = fmaf(xb, w1.x, preB);
        preA = fmaf(ya, w1.y, preA);  preB = fmaf(yb, w1.y, preB);
        preA = fmaf(za, w1.z, preA);  preB = fmaf(zb, w1.z, preB);
        float hA = softplusf(preA), hB = softplusf(preB);
        unsigned long long hA2, hB2;
        PACK2(hA2, __float_as_uint(hA));
        PACK2(hB2, __float_as_uint(hB));
        const ulonglong2* wrow = (const ulonglong2*)(sh->W2) + k * 16;
#pragma unroll
        for (int j = 0; j < 16; ++j) {
            ulonglong2 wv = wrow[j];
            FMA2(accA[2 * j + 0], hA2, wv.x);
            FMA2(accA[2 * j + 1], hA2, wv.y);
            FMA2(accB[2 * j + 0], hB2, wv.x);
            FMA2(accB[2 * j + 1], hB2, wv.y);
        }
    }
    float a0 = 0.f, a1 = 0.f, a2 = 0.f, a3 = 0.f;
    float b0 = 0.f, b1 = 0.f, b2_ = 0.f, b3_ = 0.f;
#pragma unroll
    for (int m = 0; m < 32; m += 2) {
        unsigned l0, h0, l1, h1;
        int j = 2 * m;
        UNPACK2(l0, h0, accA[m]);
        UNPACK2(l1, h1, accA[m + 1]);
        a0 = fmaf(softplusf(ADD(__uint_as_float(l0), sh->b2[j + 0])), sh->W3[j + 0], a0);
        a1 = fmaf(softplusf(ADD(__uint_as_float(h0), sh->b2[j + 1])), sh->W3[j + 1], a1);
        a2 = fmaf(softplusf(ADD(__uint_as_float(l1), sh->b2[j + 2])), sh->W3[j + 2], a2);
        a3 = fmaf(softplusf(ADD(__uint_as_float(h1), sh->b2[j + 3])), sh->W3[j + 3], a3);
        UNPACK2(l0, h0, accB[m]);
        UNPACK2(l1, h1, accB[m + 1]);
        b0 = fmaf(softplusf(ADD(__uint_as_float(l0), sh->b2[j + 0])), sh->W3[j + 0], b0);
        b1 = fmaf(softplusf(ADD(__uint_as_float(h0), sh->b2[j + 1])), sh->W3[j + 1], b1);
        b2_ = fmaf(softplusf(ADD(__uint_as_float(l1), sh->b2[j + 2])), sh->W3[j + 2], b2_);
        b3_ = fmaf(softplusf(ADD(__uint_as_float(h1), sh->b2[j + 3])), sh->W3[j + 3], b3_);
    }
    float dA = ADD(((a0 + a1) + (a2 + a3)), sh->b3);
    float dB = ADD(((b0 + b1) + (b2_ + b3_)), sh->b3);
    float rA = ADD(ADD(ADD(MUL(xa, xa), MUL(ya, ya)), MUL(za, za)), 1e-12f);
    float rB = ADD(ADD(ADD(MUL(xb, xb), MUL(yb, yb)), MUL(zb, zb)), 1e-12f);
    *oa = ADD(SUB(sqrtf(rA), 0.5f), MUL(0.05f, tanhf(dA)));
    *ob = ADD(SUB(sqrtf(rB), 0.5f), MUL(0.05f, tanhf(dB)));
}

// One sphere-tracing iteration, BOTH chains in one thread via sdf_eval2.
// Update order per chain identical to the reference (bit-identical).
__device__ __forceinline__ void trace_step2(const SdfShared* __restrict__ sh,
                                            float dx, float dy, float dz,
                                            float cx, float cy, float cz,
                                            float& accS, float& accE,
                                            float& nextS, float& nextE,
                                            bool& unfinS, bool& unfinE) {
    bool advS = unfinS && (nextS > STH);  unfinS = advS;
    bool advE = unfinE && (nextE > STH);  unfinE = advE;
    float csS = advS ? fminf(nextS, 0.5f) : 0.0f;
    float csE = advE ? fminf(nextE, 0.5f) : 0.0f;
    accS = ADD(accS, MUL(1.2f, csS));
    accE = SUB(accE, MUL(1.2f, csE));
    float va = 0.f, vb = 0.f;
    if (unfinS || unfinE)
        sdf_eval2(sh, ADD(cx, MUL(accS, dx)), ADD(cy, MUL(accS, dy)), ADD(cz, MUL(accS, dz)),
                  ADD(cx, MUL(accE, dx)), ADD(cy, MUL(accE, dy)), ADD(cz, MUL(accE, dz)),
                  &va, &vb);
    nextS = unfinS ? va : 0.0f;
    nextE = unfinE ? vb : 0.0f;
    bool lsS = nextS < 0.0f;
    bool lsE = nextE < 0.0f;
    if (lsS) accS = SUB(accS, MUL(0.5f, csS));
    if (lsE) accE = ADD(accE, MUL(0.5f, csE));
    if (lsS || lsE) {
        float va2, vb2;
        sdf_eval2(sh, ADD(cx, MUL(accS, dx)), ADD(cy, MUL(accS, dy)), ADD(cz, MUL(accS, dz)),
                  ADD(cx, MUL(accE, dx)), ADD(cy, MUL(accE, dy)), ADD(cz, MUL(accE, dz)),
                  &va2, &vb2);
        if (lsS) nextS = va2;
        if (lsE) nextE = vb2;
    }
    bool inside = accS < accE;
    unfinS = unfinS && inside;
    unfinE = unfinE && inside;
}

// ---------------- phase 0: fold latents + reset counters + mask detect ----------------
__global__ void prep_detect_kernel(const float* __restrict__ W1, const float* __restrict__ b1,
                                   const float* __restrict__ idl, const float* __restrict__ expl,
                                   const unsigned int* __restrict__ m) {
    if (blockIdx.x == 0) {
        int j = threadIdx.x;
        if (j == 0) { g_count = 0; g_scnt = 0; }
        if (j < 11) g_tcnt[j] = 0;
        if (j < 64) {
            float c = b1[j];
#pragma unroll 8
            for (int k = 0; k < 32; ++k) c = fmaf(idl[k], W1[(3 + k) * 64 + j], c);
#pragma unroll 8
            for (int k = 0; k < 32; ++k) c = fmaf(expl[k], W1[(35 + k) * 64 + j], c);
            g_c1[j] = c;
        }
    } else {
        __shared__ int any_big, any_f1, any_other;
        if (threadIdx.x == 0) { any_big = 0; any_f1 = 0; any_other = 0; }
        __syncthreads();
        for (int i = threadIdx.x; i < NRAYS / 4; i += blockDim.x) {
            unsigned v = m[i];
            if (v > 1u) {
                any_big = 1;
                if (v == 0x3F800000u) any_f1 = 1;
                else any_other = 1;
            }
        }
        __syncthreads();
        if (threadIdx.x == 0) {
            int mode;
            if (!any_big) mode = 1;
            else if (any_f1 && !any_other) mode = 2;
            else mode = 0;
            g_mask_mode = mode;
        }
    }
}

// ---------------- phase 1a: init + iteration 0 fused; 1 thread/ray ----------------
__global__ void __launch_bounds__(128)
trace_init_kernel(const float* __restrict__ cam_loc, const float* __restrict__ dirs,
                  const float* __restrict__ W1, const float* __restrict__ W2,
                  const float* __restrict__ b2, const float* __restrict__ W3,
                  const float* __restrict__ b3) {
    __shared__ SdfShared sh;
    load_shared(&sh, W1, W2, b2, W3, b3, cam_loc);

    int r = blockIdx.x * blockDim.x + threadIdx.x;
    float dx = dirs[3 * r + 0], dy = dirs[3 * r + 1], dz = dirs[3 * r + 2];
    float cx = sh.cam[0], cy = sh.cam[1], cz = sh.cam[2];

    float rcd = ADD(ADD(MUL(dx, cx), MUL(dy, cy)), MUL(dz, cz));
    float cam2 = ADD(ADD(MUL(cx, cx), MUL(cy, cy)), MUL(cz, cz));
    float under = SUB(MUL(rcd, rcd), SUB(cam2, 1.0f));   // R = 1
    bool mask = under > 0.0f;
    float sq = sqrtf(mask ? under : 1.0f);
    float accS = mask ? fmaxf(SUB(-sq, rcd), 0.0f) : 0.0f;
    float accE = mask ? fmaxf(SUB(sq, rcd), 0.0f) : 0.0f;
    bool unfinS = mask, unfinE = mask;

    float nextS = 0.f, nextE = 0.f;
    if (mask) {
        float va, vb;
        sdf_eval2(&sh, ADD(cx, MUL(accS, dx)), ADD(cy, MUL(accS, dy)), ADD(cz, MUL(accS, dz)),
                  ADD(cx, MUL(accE, dx)), ADD(cy, MUL(accE, dy)), ADD(cz, MUL(accE, dz)),
                  &va, &vb);
        nextS = va; nextE = vb;
    }
    bool no_int = (nextS < 0.0f) && (nextE < 0.0f);

    // iteration 0 (fused)
    trace_step2(&sh, dx, dy, dz, cx, cy, cz, accS, accE, nextS, nextE, unfinS, unfinE);

    g_acc_s[r] = accS;  g_next_s[r] = nextS;
    g_acc_e[r] = accE;  g_next_e[r] = nextE;
    unsigned nb = (unfinS ? 1u : 0u) | (unfinE ? 2u : 0u) | (no_int ? 4u : 0u);
    g_unfin[r] = nb;
    if (nb & 3u) {
        int pos = atomicAdd(&g_tcnt[1], 1);
        g_tlist[1][pos] = r;
    }
}

// ---------------- phase 1b: fused ladder — iterations [a, b); 1 thread/ray ----------------
// When b == 10 (final), appends sampler rays (unfin_s && next_s > STH) to g_list.
__global__ void __launch_bounds__(128)
trace_ladder_kernel(const float* __restrict__ cam_loc, const float* __restrict__ dirs,
                    const float* __restrict__ W1, const float* __restrict__ W2,
                    const float* __restrict__ b2, const float* __restrict__ W3,
                    const float* __restrict__ b3, int a, int b) {
    int cnt = g_tcnt[a];
    if (blockIdx.x * 128 >= cnt) return;         // uniform per block

    __shared__ SdfShared sh;
    load_shared(&sh, W1, W2, b2, W3, b3, cam_loc);

    int i = blockIdx.x * 128 + threadIdx.x;
    if (i >= cnt) return;
    int r = g_tlist[a][i];

    float dx = dirs[3 * r + 0], dy = dirs[3 * r + 1], dz = dirs[3 * r + 2];
    float cx = sh.cam[0], cy = sh.cam[1], cz = sh.cam[2];

    float accS = g_acc_s[r], nextS = g_next_s[r];
    float accE = g_acc_e[r], nextE = g_next_e[r];
    unsigned ub = g_unfin[r];
    bool unfinS = ub & 1u, unfinE = (ub >> 1) & 1u;

    for (int it = a; it < b; ++it)
        trace_step2(&sh, dx, dy, dz, cx, cy, cz, accS, accE, nextS, nextE, unfinS, unfinE);

    g_acc_s[r] = accS;  g_next_s[r] = nextS;
    g_acc_e[r] = accE;  g_next_e[r] = nextE;
    unsigned nb = (unfinS ? 1u : 0u) | (unfinE ? 2u : 0u) | (ub & 4u);
    g_unfin[r] = nb;
    if (b < 10) {
        if (nb & 3u) {
            int pos = atomicAdd(&g_tcnt[b], 1);
            g_tlist[b][pos] = r;
        }
    } else {
        // final: sampler = unfin_s after final threshold check (it==10)
        if (unfinS && (nextS > STH)) {
            int pos = atomicAdd(&g_count, 1);
            g_list[pos] = r;
        }
    }
}

// ---------------- phase 2: compacted sampler — two samples per thread ----------------
__global__ void __launch_bounds__(128, 1)
sample_kernel(const float* __restrict__ cam_loc, const float* __restrict__ dirs,
              const float* __restrict__ W1, const float* __restrict__ W2,
              const float* __restrict__ b2, const float* __restrict__ W3,
              const float* __restrict__ b3) {
    int cnt = g_count;
    int nwork = 50 * cnt;
    if (blockIdx.x * 128 >= nwork) return;

    __shared__ SdfShared sh;
    load_shared(&sh, W1, W2, b2, W3, b3, cam_loc);

    int t = blockIdx.x * 128 + threadIdx.x;
    if (t >= nwork) return;
    int i = t / 50;
    int s = t - 50 * i;
    int r = g_list[i];

    float mn = g_acc_s[r], mx = g_acc_e[r];
    float dlt = SUB(mx, mn);
    float dx = dirs[3 * r + 0], dy = dirs[3 * r + 1], dz = dirs[3 * r + 2];

    float ta = MUL((float)s, 1.0f / 99.0f);
    float da = ADD(mn, MUL(ta, dlt));
    float xa = ADD(sh.cam[0], MUL(da, dx));
    float ya = ADD(sh.cam[1], MUL(da, dy));
    float za = ADD(sh.cam[2], MUL(da, dz));

    float tb = MUL((float)(s + 50), 1.0f / 99.0f);
    float db = ADD(mn, MUL(tb, dlt));
    float xb = ADD(sh.cam[0], MUL(db, dx));
    float yb = ADD(sh.cam[1], MUL(db, dy));
    float zb = ADD(sh.cam[2], MUL(db, dz));

    float va, vb;
    sdf_eval2(&sh, xa, ya, za, xb, yb, zb, &va, &vb);
    g_sdfval[s * NRAYS + r] = va;
    g_sdfval[(s + 50) * NRAYS + r] = vb;
}

// ---------------- phase 3a: flags + argmins + provisional outputs + secant compaction ----------------
__global__ void finish_a_kernel(const float* __restrict__ cam_loc, const float* __restrict__ dirs,
                                const void* __restrict__ objmask, float* __restrict__ out) {
    int r = blockIdx.x * blockDim.x + threadIdx.x;
    unsigned ub = g_unfin[r];
    float acc_s = g_acc_s[r];
    float acc_e = g_acc_e[r];
    bool sampler = (ub & 1u) && (g_next_s[r] > STH);
    bool netobj = (acc_s < acc_e) && !(ub & 4u);

    float dx = dirs[3 * r + 0], dy = dirs[3 * r + 1], dz = dirs[3 * r + 2];
    float cx = cam_loc[0], cy = cam_loc[1], cz = cam_loc[2];

    float out_d, out_m;
    if (!sampler) {
        out_d = acc_s;
        out_m = netobj ? 1.0f : 0.0f;
    } else {
        float mn = acc_s, mx = acc_e;
        float dlt = SUB(mx, mn);
        float best1 = 1e30f; int ind = 0;
        float best2 = 1e30f; int ind_out = 0;
        for (int s = 0; s < NSTEPS; ++s) {
            float v = g_sdfval[s * NRAYS + r];
            float sg = (v > 0.f) ? 1.f : ((v < 0.f) ? -1.f : 0.f);
            float m1 = sg * (float)(NSTEPS - s);
            if (m1 < best1) { best1 = m1; ind = s; }
            if (v < best2) { best2 = v; ind_out = s; }
        }
        float d_at = ADD(mn, MUL(MUL((float)ind, 1.f / 99.f), dlt));
        float sdf_at = g_sdfval[ind * NRAYS + r];
        bool net_surf = sdf_at < 0.f;
        int mode = g_mask_mode;
        bool obj = (mode == 1) ? (((const int*)objmask)[r] != 0)
                 : (mode == 2) ? (((const float*)objmask)[r] != 0.0f)
                               : (((const unsigned char*)objmask)[r] != 0);
        bool p_out = !(obj && net_surf);
        if (p_out) {
            out_d = ADD(mn, MUL(MUL((float)ind_out, 1.f / 99.f), dlt));
        } else {
            int ind_lo = (ind == 0) ? (NSTEPS - 1) : (ind - 1);
            int pos = atomicAdd(&g_scnt, 1);
            g_slist[pos] = r;
            g_szh[pos] = d_at;
            g_ssh[pos] = sdf_at;
            g_szl[pos] = ADD(mn, MUL(MUL((float)ind_lo, 1.f / 99.f), dlt));
            g_ssl[pos] = g_sdfval[ind_lo * NRAYS + r];
            out_d = d_at;
        }
        out_m = net_surf ? 1.0f : 0.0f;
    }

    out[3 * r + 0] = ADD(cx, MUL(out_d, dx));
    out[3 * r + 1] = ADD(cy, MUL(out_d, dy));
    out[3 * r + 2] = ADD(cz, MUL(out_d, dz));
    out[3 * NRAYS + r] = out_m;
    out[4 * NRAYS + r] = out_d;
}

// ---------------- phase 3b: compacted secant refinement ----------------
__global__ void __launch_bounds__(128, 1)
finish_b_kernel(const float* __restrict__ cam_loc, const float* __restrict__ dirs,
                const float* __restrict__ W1, const float* __restrict__ W2,
                const float* __restrict__ b2, const float* __restrict__ W3,
                const float* __restrict__ b3, float* __restrict__ out) {
    int cnt = g_scnt;
    if (blockIdx.x * 128 >= cnt) return;

    __shared__ SdfShared sh;
    load_shared(&sh, W1, W2, b2, W3, b3, cam_loc);

    int t = blockIdx.x * 128 + threadIdx.x;
    if (t >= cnt) return;
    int r = g_slist[t];
    float dx = dirs[3 * r + 0], dy = dirs[3 * r + 1], dz = dirs[3 * r + 2];
    float cx = sh.cam[0], cy = sh.cam[1], cz = sh.cam[2];

    float z_low = g_szl[t], z_high = g_szh[t];
    float sdf_low = g_ssl[t], sdf_high = g_ssh[t];
    float denom = SUB(sdf_high, sdf_low);
    float z_pred = ADD(__fdiv_rn(MUL(-sdf_low, SUB(z_high, z_low)),
                                 (denom == 0.f) ? 1.f : denom), z_low);
    for (int i = 0; i < 8; ++i) {
        float sm = sdf_eval(&sh, ADD(cx, MUL(z_pred, dx)), ADD(cy, MUL(z_pred, dy)),
                            ADD(cz, MUL(z_pred, dz)));
        if (sm > 0.f) { z_low = z_pred; sdf_low = sm; }
        if (sm < 0.f) { z_high = z_pred; sdf_high = sm; }
        denom = SUB(sdf_high, sdf_low);
        z_pred = ADD(__fdiv_rn(MUL(-sdf_low, SUB(z_high, z_low)),
                               (denom == 0.f) ? 1.f : denom), z_low);
    }
    out[3 * r + 0] = ADD(cx, MUL(z_pred, dx));
    out[3 * r + 1] = ADD(cy, MUL(z_pred, dy));
    out[3 * r + 2] = ADD(cz, MUL(z_pred, dz));
    out[4 * NRAYS + r] = z_pred;               // out_m already correct (net_surf=1)
}

extern "C" void kernel_launch(void* const* d_in, const int* in_sizes, int n_in,
                              void* d_out, int out_size) {
    const float* cam   = (const float*)d_in[0];
    const void*  omask = d_in[1];
    const float* dirs  = (const float*)d_in[2];
    const float* idl   = (const float*)d_in[3];
    const float* expl  = (const float*)d_in[4];
    const float* W1    = (const float*)d_in[5];
    const float* b1    = (const float*)d_in[6];
    const float* W2    = (const float*)d_in[7];
    const float* b2    = (const float*)d_in[8];
    const float* W3    = (const float*)d_in[9];
    const float* b3    = (const float*)d_in[10];
    float* out = (float*)d_out;

    prep_detect_kernel<<<2, 256>>>(W1, b1, idl, expl, (const unsigned int*)omask);
    trace_init_kernel<<<NRAYS / 128, 128>>>(cam, dirs, W1, W2, b2, W3, b3);
    trace_ladder_kernel<<<NRAYS / 128, 128>>>(cam, dirs, W1, W2, b2, W3, b3, 1, 3);
    trace_ladder_kernel<<<NRAYS / 128, 128>>>(cam, dirs, W1, W2, b2, W3, b3, 3, 5);
    trace_ladder_kernel<<<NRAYS / 128, 128>>>(cam, dirs, W1, W2, b2, W3, b3, 5, 7);
    trace_ladder_kernel<<<NRAYS / 128, 128>>>(cam, dirs, W1, W2, b2, W3, b3, 7, 9);
    trace_ladder_kernel<<<NRAYS / 128, 128>>>(cam, dirs, W1, W2, b2, W3, b3, 9, 10);
    sample_kernel<<<(50 * NRAYS) / 128, 128>>>(cam, dirs, W1, W2, b2, W3, b3);
    finish_a_kernel<<<NRAYS / 256, 256>>>(cam, dirs, omask, out);
    finish_b_kernel<<<NRAYS / 128, 128>>>(cam, dirs, W1, W2, b2, W3, b3, out);
}

// round 15
// speedup vs baseline: 1.4119x; 1.4119x over previous
#include <cuda_runtime.h>

#define NRAYS 16384
#define NSTEPS 100
#define STH 5e-5f

// ---------------- device scratch (no allocations allowed) ----------------
__device__ float g_c1[64];
__device__ float g_acc_s[NRAYS];
__device__ float g_acc_e[NRAYS];
__device__ float g_next_s[NRAYS];
__device__ float g_next_e[NRAYS];
__device__ unsigned char g_unfin[NRAYS];         // bit0 unfin_s, bit1 unfin_e, bit2 no_int
__device__ float g_sdfval[NSTEPS * NRAYS];       // sample-major: [s*NRAYS + r]
__device__ int g_mask_mode;                      // 0=bytes, 1=int32 words, 2=float32 words
__device__ int g_count;                          // number of sampler rays
__device__ int g_list[NRAYS];                    // compacted sampler-ray indices
__device__ int g_tcnt[11];                       // active-ray count per trace iteration
__device__ int g_tlist[11][NRAYS];               // active-ray lists per trace iteration
__device__ int g_scnt;                           // secant ray count
__device__ int g_slist[NRAYS];                   // secant ray indices
__device__ float g_szl[NRAYS], g_szh[NRAYS], g_ssl[NRAYS], g_ssh[NRAYS];

// Exact XLA-style elementwise ops: separate RN mul/add (no FMA contraction).
#define MUL(a, b) __fmul_rn((a), (b))
#define ADD(a, b) __fadd_rn((a), (b))
#define SUB(a, b) __fsub_rn((a), (b))

// Packed f32x2 ops (sm_100+). Each half rounds exactly like scalar IEEE FMA.
#define FMA2(acc, a, b) \
    asm("fma.rn.f32x2 %0, %1, %2, %0;" : "+l"(acc) : "l"(a), "l"(b))
#define PACK2(d, s) \
    asm("mov.b64 %0, {%1, %1};" : "=l"(d) : "r"(s))
#define UNPACK2(lo, hi, v) \
    asm("mov.b64 {%0, %1}, %2;" : "=r"(lo), "=r"(hi) : "l"(v))

// ---------------- shared weight cache ----------------
struct __align__(16) SdfShared {
    float4 W1p[64];     // {W1x[k], W1y[k], W1z[k], c1[k]}
    float b2[64];
    float W3[64];
    float W2[64 * 64];  // row-major [k][j]
    float cam[3];
    float b3;
};

__device__ __forceinline__ float softplusf(float x) {
    return ADD(fmaxf(x, 0.0f), __logf(__fadd_rn(1.0f, __expf(-fabsf(x)))));
}

__device__ __forceinline__ void load_shared(SdfShared* sh, const float* W1, const float* W2,
                                            const float* b2, const float* W3, const float* b3,
                                            const float* cam) {
    int t = threadIdx.x, nt = blockDim.x;
    for (int i = t; i < 64 * 64; i += nt) sh->W2[i] = W2[i];
    for (int i = t; i < 64; i += nt) {
        sh->W1p[i] = make_float4(W1[i], W1[64 + i], W1[128 + i], g_c1[i]);
        sh->b2[i] = b2[i];
        sh->W3[i] = W3[i];
    }
    if (t == 0) {
        sh->b3 = b3[0];
        sh->cam[0] = cam[0]; sh->cam[1] = cam[1]; sh->cam[2] = cam[2];
    }
    __syncthreads();
}

// Single-sample SDF eval. Layer-2 in packed f32x2 FMA (bit-identical to scalar).
// Unroll 8: accumulation stays k-sequential per column -> bit-identical.
__device__ __noinline__ float sdf_eval(const SdfShared* __restrict__ sh,
                                       float x, float y, float z) {
    unsigned long long acc2[32];
#pragma unroll
    for (int m = 0; m < 32; ++m) acc2[m] = 0ull;
#pragma unroll 8
    for (int k = 0; k < 64; ++k) {
        float4 w1 = sh->W1p[k];
        float pre = w1.w;
        pre = fmaf(x, w1.x, pre);
        pre = fmaf(y, w1.y, pre);
        pre = fmaf(z, w1.z, pre);
        float hk = softplusf(pre);
        unsigned long long hk2;
        PACK2(hk2, __float_as_uint(hk));
        const ulonglong2* wrow = (const ulonglong2*)(sh->W2) + k * 16;
#pragma unroll
        for (int j = 0; j < 16; ++j) {
            ulonglong2 wv = wrow[j];
            FMA2(acc2[2 * j + 0], hk2, wv.x);
            FMA2(acc2[2 * j + 1], hk2, wv.y);
        }
    }
    float d0 = 0.f, d1 = 0.f, d2 = 0.f, d3 = 0.f;
#pragma unroll
    for (int m = 0; m < 32; m += 2) {
        unsigned l0, h0, l1, h1;
        UNPACK2(l0, h0, acc2[m]);
        UNPACK2(l1, h1, acc2[m + 1]);
        int j = 2 * m;
        d0 = fmaf(softplusf(ADD(__uint_as_float(l0), sh->b2[j + 0])), sh->W3[j + 0], d0);
        d1 = fmaf(softplusf(ADD(__uint_as_float(h0), sh->b2[j + 1])), sh->W3[j + 1], d1);
        d2 = fmaf(softplusf(ADD(__uint_as_float(l1), sh->b2[j + 2])), sh->W3[j + 2], d2);
        d3 = fmaf(softplusf(ADD(__uint_as_float(h1), sh->b2[j + 3])), sh->W3[j + 3], d3);
    }
    float delta = ADD(((d0 + d1) + (d2 + d3)), sh->b3);
    float r2 = ADD(ADD(ADD(MUL(x, x), MUL(y, y)), MUL(z, z)), 1e-12f);
    return ADD(SUB(sqrtf(r2), 0.5f), MUL(0.05f, tanhf(delta)));
}

// Two-sample SDF eval (sample kernel): amortizes weight loads over two evals.
__device__ __noinline__ void sdf_eval2(const SdfShared* __restrict__ sh,
                                       float xa, float ya, float za,
                                       float xb, float yb, float zb,
                                       float* __restrict__ oa, float* __restrict__ ob) {
    unsigned long long accA[32], accB[32];
#pragma unroll
    for (int m = 0; m < 32; ++m) { accA[m] = 0ull; accB[m] = 0ull; }
#pragma unroll 2
    for (int k = 0; k < 64; ++k) {
        float4 w1 = sh->W1p[k];
        float preA = w1.w, preB = w1.w;
        preA = fmaf(xa, w1.x, preA);  preB = fmaf(xb, w1.x, preB);
        preA = fmaf(ya, w1.y, preA);  preB = fmaf(yb, w1.y, preB);
        preA = fmaf(za, w1.z, preA);  preB = fmaf(zb, w1.z, preB);
        float hA = softplusf(preA), hB = softplusf(preB);
        unsigned long long hA2, hB2;
        PACK2(hA2, __float_as_uint(hA));
        PACK2(hB2, __float_as_uint(hB));
        const ulonglong2* wrow = (const ulonglong2*)(sh->W2) + k * 16;
#pragma unroll
        for (int j = 0; j < 16; ++j) {
            ulonglong2 wv = wrow[j];
            FMA2(accA[2 * j + 0], hA2, wv.x);
            FMA2(accA[2 * j + 1], hA2, wv.y);
            FMA2(accB[2 * j + 0], hB2, wv.x);
            FMA2(accB[2 * j + 1], hB2, wv.y);
        }
    }
    float a0 = 0.f, a1 = 0.f, a2 = 0.f, a3 = 0.f;
    float b0 = 0.f, b1 = 0.f, b2_ = 0.f, b3_ = 0.f;
#pragma unroll
    for (int m = 0; m < 32; m += 2) {
        unsigned l0, h0, l1, h1;
        int j = 2 * m;
        UNPACK2(l0, h0, accA[m]);
        UNPACK2(l1, h1, accA[m + 1]);
        a0 = fmaf(softplusf(ADD(__uint_as_float(l0), sh->b2[j + 0])), sh->W3[j + 0], a0);
        a1 = fmaf(softplusf(ADD(__uint_as_float(h0), sh->b2[j + 1])), sh->W3[j + 1], a1);
        a2 = fmaf(softplusf(ADD(__uint_as_float(l1), sh->b2[j + 2])), sh->W3[j + 2], a2);
        a3 = fmaf(softplusf(ADD(__uint_as_float(h1), sh->b2[j + 3])), sh->W3[j + 3], a3);
        UNPACK2(l0, h0, accB[m]);
        UNPACK2(l1, h1, accB[m + 1]);
        b0 = fmaf(softplusf(ADD(__uint_as_float(l0), sh->b2[j + 0])), sh->W3[j + 0], b0);
        b1 = fmaf(softplusf(ADD(__uint_as_float(h0), sh->b2[j + 1])), sh->W3[j + 1], b1);
        b2_ = fmaf(softplusf(ADD(__uint_as_float(l1), sh->b2[j + 2])), sh->W3[j + 2], b2_);
        b3_ = fmaf(softplusf(ADD(__uint_as_float(h1), sh->b2[j + 3])), sh->W3[j + 3], b3_);
    }
    float dA = ADD(((a0 + a1) + (a2 + a3)), sh->b3);
    float dB = ADD(((b0 + b1) + (b2_ + b3_)), sh->b3);
    float rA = ADD(ADD(ADD(MUL(xa, xa), MUL(ya, ya)), MUL(za, za)), 1e-12f);
    float rB = ADD(ADD(ADD(MUL(xb, xb), MUL(yb, yb)), MUL(zb, zb)), 1e-12f);
    *oa = ADD(SUB(sqrtf(rA), 0.5f), MUL(0.05f, tanhf(dA)));
    *ob = ADD(SUB(sqrtf(rB), 0.5f), MUL(0.05f, tanhf(dB)));
}

// One sphere-tracing iteration for chain c of ray r (bit-identical to R12/R13).
__device__ __forceinline__ void trace_step(const SdfShared* __restrict__ sh,
                                           float dx, float dy, float dz,
                                           float cx, float cy, float cz,
                                           int c, unsigned mask2,
                                           float& acc, float& next, bool& unfin) {
    bool adv = unfin && (next > STH);
    unfin = adv;
    float cs = adv ? fminf(next, 0.5f) : 0.0f;   // clip(-0.5,0.5): next > STH > 0
    float st = MUL(1.2f, cs);
    acc = c ? SUB(acc, st) : ADD(acc, st);
    next = unfin ? sdf_eval(sh, ADD(cx, MUL(acc, dx)), ADD(cy, MUL(acc, dy)),
                            ADD(cz, MUL(acc, dz)))
                 : 0.0f;
    if (next < 0.0f) {                           // line-search (1 iter, step=0.5)
        float ls = MUL(0.5f, cs);
        acc = c ? ADD(acc, ls) : SUB(acc, ls);
        next = sdf_eval(sh, ADD(cx, MUL(acc, dx)), ADD(cy, MUL(acc, dy)),
                        ADD(cz, MUL(acc, dz)));
    }
    float acc_o = __shfl_xor_sync(mask2, acc, 1);
    bool inside = c ? (acc_o < acc) : (acc < acc_o);
    unfin = unfin && inside;
}

// ---------------- phase 0: fold latents + reset counters + mask detect ----------------
__global__ void prep_detect_kernel(const float* __restrict__ W1, const float* __restrict__ b1,
                                   const float* __restrict__ idl, const float* __restrict__ expl,
                                   const unsigned int* __restrict__ m) {
    if (blockIdx.x == 0) {
        int j = threadIdx.x;
        if (j == 0) { g_count = 0; g_scnt = 0; }
        if (j < 11) g_tcnt[j] = 0;
        if (j < 64) {
            float c = b1[j];
#pragma unroll 8
            for (int k = 0; k < 32; ++k) c = fmaf(idl[k], W1[(3 + k) * 64 + j], c);
#pragma unroll 8
            for (int k = 0; k < 32; ++k) c = fmaf(expl[k], W1[(35 + k) * 64 + j], c);
            g_c1[j] = c;
        }
    } else {
        __shared__ int any_big, any_f1, any_other;
        if (threadIdx.x == 0) { any_big = 0; any_f1 = 0; any_other = 0; }
        __syncthreads();
        for (int i = threadIdx.x; i < NRAYS / 4; i += blockDim.x) {
            unsigned v = m[i];
            if (v > 1u) {
                any_big = 1;
                if (v == 0x3F800000u) any_f1 = 1;
                else any_other = 1;
            }
        }
        __syncthreads();
        if (threadIdx.x == 0) {
            int mode;
            if (!any_big) mode = 1;
            else if (any_f1 && !any_other) mode = 2;
            else mode = 0;
            g_mask_mode = mode;
        }
    }
}

// ---------------- phase 1a: init + iteration 0 fused ----------------
__global__ void __launch_bounds__(128)
trace_init_kernel(const float* __restrict__ cam_loc, const float* __restrict__ dirs,
                  const float* __restrict__ W1, const float* __restrict__ W2,
                  const float* __restrict__ b2, const float* __restrict__ W3,
                  const float* __restrict__ b3) {
    __shared__ SdfShared sh;
    load_shared(&sh, W1, W2, b2, W3, b3, cam_loc);

    int gid = blockIdx.x * blockDim.x + threadIdx.x;
    int r = gid >> 1;
    int c = gid & 1;                 // 0 = start chain, 1 = end chain
    int lane = threadIdx.x & 31;
    unsigned mask2 = 0x3u << (lane & ~1);
    float dx = dirs[3 * r + 0], dy = dirs[3 * r + 1], dz = dirs[3 * r + 2];
    float cx = sh.cam[0], cy = sh.cam[1], cz = sh.cam[2];

    float rcd = ADD(ADD(MUL(dx, cx), MUL(dy, cy)), MUL(dz, cz));
    float cam2 = ADD(ADD(MUL(cx, cx), MUL(cy, cy)), MUL(cz, cz));
    float under = SUB(MUL(rcd, rcd), SUB(cam2, 1.0f));   // R = 1
    bool mask = under > 0.0f;
    float sq = sqrtf(mask ? under : 1.0f);
    float acc = mask ? fmaxf(SUB((c ? sq : -sq), rcd), 0.0f) : 0.0f;
    bool unfin = mask;

    float next = 0.0f;
    if (mask)
        next = sdf_eval(&sh, ADD(cx, MUL(acc, dx)), ADD(cy, MUL(acc, dy)), ADD(cz, MUL(acc, dz)));
    float next_o = __shfl_xor_sync(0xffffffffu, next, 1);
    bool no_int = (next < 0.0f) && (next_o < 0.0f);

    // iteration 0 (fused)
    trace_step(&sh, dx, dy, dz, cx, cy, cz, c, mask2, acc, next, unfin);

    if (c) { g_acc_e[r] = acc; g_next_e[r] = next; }
    else   { g_acc_s[r] = acc; g_next_s[r] = next; }
    unsigned ob = __shfl_xor_sync(mask2, (unsigned)unfin, 1);
    if (c == 0) {
        unsigned nb = (unfin ? 1u : 0u) | (ob ? 2u : 0u) | (no_int ? 4u : 0u);
        g_unfin[r] = nb;
        if (nb & 3u) {
            int pos = atomicAdd(&g_tcnt[1], 1);
            g_tlist[1][pos] = r;
        }
    }
}

// ---------------- phase 1b: fused ladder — iterations [a, b) over the active list ----------------
// When b == 10 (final), appends sampler rays (unfin_s && next_s > STH) to g_list.
__global__ void __launch_bounds__(128)
trace_ladder_kernel(const float* __restrict__ cam_loc, const float* __restrict__ dirs,
                    const float* __restrict__ W1, const float* __restrict__ W2,
                    const float* __restrict__ b2, const float* __restrict__ W3,
                    const float* __restrict__ b3, int a, int b) {
    int cnt = g_tcnt[a];
    if (blockIdx.x * 128 >= 2 * cnt) return;     // uniform per block

    __shared__ SdfShared sh;
    load_shared(&sh, W1, W2, b2, W3, b3, cam_loc);

    int t = blockIdx.x * 128 + threadIdx.x;
    if (t >= 2 * cnt) return;                    // pairs stay together (2*cnt even)
    int i = t >> 1;
    int c = t & 1;
    int lane = threadIdx.x & 31;
    unsigned mask2 = 0x3u << (lane & ~1);
    int r = g_tlist[a][i];

    float dx = dirs[3 * r + 0], dy = dirs[3 * r + 1], dz = dirs[3 * r + 2];
    float cx = sh.cam[0], cy = sh.cam[1], cz = sh.cam[2];

    float acc = c ? g_acc_e[r] : g_acc_s[r];
    float next = c ? g_next_e[r] : g_next_s[r];
    unsigned ub = g_unfin[r];
    bool unfin = (ub >> c) & 1u;

    for (int it = a; it < b; ++it)
        trace_step(&sh, dx, dy, dz, cx, cy, cz, c, mask2, acc, next, unfin);

    if (c) { g_acc_e[r] = acc; g_next_e[r] = next; }
    else   { g_acc_s[r] = acc; g_next_s[r] = next; }
    unsigned ob = __shfl_xor_sync(mask2, (unsigned)unfin, 1);
    if (c == 0) {
        unsigned nb = (unfin ? 1u : 0u) | (ob ? 2u : 0u) | (ub & 4u);
        g_unfin[r] = nb;
        if (b < 10) {
            if (nb & 3u) {
                int pos = atomicAdd(&g_tcnt[b], 1);
                g_tlist[b][pos] = r;
            }
        } else {
            // final: sampler = unfin_s after final threshold check (it==10)
            if (unfin && (next > STH)) {
                int pos = atomicAdd(&g_count, 1);
                g_list[pos] = r;
            }
        }
    }
}

// ---------------- phase 2: compacted sampler — two samples per thread ----------------
__global__ void __launch_bounds__(128, 1)
sample_kernel(const float* __restrict__ cam_loc, const float* __restrict__ dirs,
              const float* __restrict__ W1, const float* __restrict__ W2,
              const float* __restrict__ b2, const float* __restrict__ W3,
              const float* __restrict__ b3) {
    int cnt = g_count;
    int nwork = 50 * cnt;
    if (blockIdx.x * 128 >= nwork) return;

    __shared__ SdfShared sh;
    load_shared(&sh, W1, W2, b2, W3, b3, cam_loc);

    int t = blockIdx.x * 128 + threadIdx.x;
    if (t >= nwork) return;
    int i = t / 50;
    int s = t - 50 * i;
    int r = g_list[i];

    float mn = g_acc_s[r], mx = g_acc_e[r];
    float dlt = SUB(mx, mn);
    float dx = dirs[3 * r + 0], dy = dirs[3 * r + 1], dz = dirs[3 * r + 2];

    float ta = MUL((float)s, 1.0f / 99.0f);
    float da = ADD(mn, MUL(ta, dlt));
    float xa = ADD(sh.cam[0], MUL(da, dx));
    float ya = ADD(sh.cam[1], MUL(da, dy));
    float za = ADD(sh.cam[2], MUL(da, dz));

    float tb = MUL((float)(s + 50), 1.0f / 99.0f);
    float db = ADD(mn, MUL(tb, dlt));
    float xb = ADD(sh.cam[0], MUL(db, dx));
    float yb = ADD(sh.cam[1], MUL(db, dy));
    float zb = ADD(sh.cam[2], MUL(db, dz));

    float va, vb;
    sdf_eval2(&sh, xa, ya, za, xb, yb, zb, &va, &vb);
    g_sdfval[s * NRAYS + r] = va;
    g_sdfval[(s + 50) * NRAYS + r] = vb;
}

// ---------------- phase 3a: flags + argmins + provisional outputs + secant compaction ----------------
__global__ void finish_a_kernel(const float* __restrict__ cam_loc, const float* __restrict__ dirs,
                                const void* __restrict__ objmask, float* __restrict__ out) {
    int r = blockIdx.x * blockDim.x + threadIdx.x;
    unsigned ub = g_unfin[r];
    float acc_s = g_acc_s[r];
    float acc_e = g_acc_e[r];
    bool sampler = (ub & 1u) && (g_next_s[r] > STH);     // == trace_final's criterion
    bool netobj = (acc_s < acc_e) && !(ub & 4u);

    float dx = dirs[3 * r + 0], dy = dirs[3 * r + 1], dz = dirs[3 * r + 2];
    float cx = cam_loc[0], cy = cam_loc[1], cz = cam_loc[2];

    float out_d, out_m;
    if (!sampler) {
        out_d = acc_s;
        out_m = netobj ? 1.0f : 0.0f;
    } else {
        float mn = acc_s, mx = acc_e;
        float dlt = SUB(mx, mn);
        float best1 = 1e30f; int ind = 0;
        float best2 = 1e30f; int ind_out = 0;
        for (int s = 0; s < NSTEPS; ++s) {
            float v = g_sdfval[s * NRAYS + r];
            float sg = (v > 0.f) ? 1.f : ((v < 0.f) ? -1.f : 0.f);
            float m1 = sg * (float)(NSTEPS - s);
            if (m1 < best1) { best1 = m1; ind = s; }
            if (v < best2) { best2 = v; ind_out = s; }
        }
        float d_at = ADD(mn, MUL(MUL((float)ind, 1.f / 99.f), dlt));
        float sdf_at = g_sdfval[ind * NRAYS + r];
        bool net_surf = sdf_at < 0.f;
        int mode = g_mask_mode;
        bool obj = (mode == 1) ? (((const int*)objmask)[r] != 0)
                 : (mode == 2) ? (((const float*)objmask)[r] != 0.0f)
                               : (((const unsigned char*)objmask)[r] != 0);
        bool p_out = !(obj && net_surf);
        if (p_out) {
            out_d = ADD(mn, MUL(MUL((float)ind_out, 1.f / 99.f), dlt));
        } else {
            int ind_lo = (ind == 0) ? (NSTEPS - 1) : (ind - 1);
            int pos = atomicAdd(&g_scnt, 1);
            g_slist[pos] = r;
            g_szh[pos] = d_at;
            g_ssh[pos] = sdf_at;
            g_szl[pos] = ADD(mn, MUL(MUL((float)ind_lo, 1.f / 99.f), dlt));
            g_ssl[pos] = g_sdfval[ind_lo * NRAYS + r];
            out_d = d_at;
        }
        out_m = net_surf ? 1.0f : 0.0f;
    }

    out[3 * r + 0] = ADD(cx, MUL(out_d, dx));
    out[3 * r + 1] = ADD(cy, MUL(out_d, dy));
    out[3 * r + 2] = ADD(cz, MUL(out_d, dz));
    out[3 * NRAYS + r] = out_m;
    out[4 * NRAYS + r] = out_d;
}

// ---------------- phase 3b: compacted secant refinement ----------------
__global__ void __launch_bounds__(128, 1)
finish_b_kernel(const float* __restrict__ cam_loc, const float* __restrict__ dirs,
                const float* __restrict__ W1, const float* __restrict__ W2,
                const float* __restrict__ b2, const float* __restrict__ W3,
                const float* __restrict__ b3, float* __restrict__ out) {
    int cnt = g_scnt;
    if (blockIdx.x * 128 >= cnt) return;

    __shared__ SdfShared sh;
    load_shared(&sh, W1, W2, b2, W3, b3, cam_loc);

    int t = blockIdx.x * 128 + threadIdx.x;
    if (t >= cnt) return;
    int r = g_slist[t];
    float dx = dirs[3 * r + 0], dy = dirs[3 * r + 1], dz = dirs[3 * r + 2];
    float cx = sh.cam[0], cy = sh.cam[1], cz = sh.cam[2];

    float z_low = g_szl[t], z_high = g_szh[t];
    float sdf_low = g_ssl[t], sdf_high = g_ssh[t];
    float denom = SUB(sdf_high, sdf_low);
    float z_pred = ADD(__fdiv_rn(MUL(-sdf_low, SUB(z_high, z_low)),
                                 (denom == 0.f) ? 1.f : denom), z_low);
    for (int i = 0; i < 8; ++i) {
        float sm = sdf_eval(&sh, ADD(cx, MUL(z_pred, dx)), ADD(cy, MUL(z_pred, dy)),
                            ADD(cz, MUL(z_pred, dz)));
        if (sm > 0.f) { z_low = z_pred; sdf_low = sm; }
        if (sm < 0.f) { z_high = z_pred; sdf_high = sm; }
        denom = SUB(sdf_high, sdf_low);
        z_pred = ADD(__fdiv_rn(MUL(-sdf_low, SUB(z_high, z_low)),
                               (denom == 0.f) ? 1.f : denom), z_low);
    }
    out[3 * r + 0] = ADD(cx, MUL(z_pred, dx));
    out[3 * r + 1] = ADD(cy, MUL(z_pred, dy));
    out[3 * r + 2] = ADD(cz, MUL(z_pred, dz));
    out[4 * NRAYS + r] = z_pred;               // out_m already correct (net_surf=1)
}

extern "C" void kernel_launch(void* const* d_in, const int* in_sizes, int n_in,
                              void* d_out, int out_size) {
    const float* cam   = (const float*)d_in[0];
    const void*  omask = d_in[1];
    const float* dirs  = (const float*)d_in[2];
    const float* idl   = (const float*)d_in[3];
    const float* expl  = (const float*)d_in[4];
    const float* W1    = (const float*)d_in[5];
    const float* b1    = (const float*)d_in[6];
    const float* W2    = (const float*)d_in[7];
    const float* b2    = (const float*)d_in[8];
    const float* W3    = (const float*)d_in[9];
    const float* b3    = (const float*)d_in[10];
    float* out = (float*)d_out;

    prep_detect_kernel<<<2, 256>>>(W1, b1, idl, expl, (const unsigned int*)omask);
    trace_init_kernel<<<(2 * NRAYS) / 128, 128>>>(cam, dirs, W1, W2, b2, W3, b3);
    trace_ladder_kernel<<<(2 * NRAYS) / 128, 128>>>(cam, dirs, W1, W2, b2, W3, b3, 1, 3);
    trace_ladder_kernel<<<(2 * NRAYS) / 128, 128>>>(cam, dirs, W1, W2, b2, W3, b3, 3, 5);
    trace_ladder_kernel<<<(2 * NRAYS) / 128, 128>>>(cam, dirs, W1, W2, b2, W3, b3, 5, 7);
    trace_ladder_kernel<<<(2 * NRAYS) / 128, 128>>>(cam, dirs, W1, W2, b2, W3, b3, 7, 9);
    trace_ladder_kernel<<<(2 * NRAYS) / 128, 128>>>(cam, dirs, W1, W2, b2, W3, b3, 9, 10);
    sample_kernel<<<(50 * NRAYS) / 128, 128>>>(cam, dirs, W1, W2, b2, W3, b3);
    finish_a_kernel<<<NRAYS / 256, 256>>>(cam, dirs, omask, out);
    finish_b_kernel<<<NRAYS / 128, 128>>>(cam, dirs, W1, W2, b2, W3, b3, out);
}

// round 16
// speedup vs baseline: 1.4159x; 1.0028x over previous
#include <cuda_runtime.h>

#define NRAYS 16384
#define NSTEPS 100
#define STH 5e-5f

// ---------------- device scratch (no allocations allowed) ----------------
__device__ float g_c1[64];
__device__ float g_acc_s[NRAYS];
__device__ float g_acc_e[NRAYS];
__device__ float g_next_s[NRAYS];
__device__ float g_next_e[NRAYS];
__device__ unsigned char g_unfin[NRAYS];         // bit0 unfin_s, bit1 unfin_e, bit2 no_int
__device__ float g_sdfval[NSTEPS * NRAYS];       // sample-major: [s*NRAYS + r]
__device__ int g_mask_mode;                      // 0=bytes, 1=int32 words, 2=float32 words
__device__ int g_count;                          // number of sampler rays
__device__ int g_list[NRAYS];                    // compacted sampler-ray indices
__device__ int g_tcnt[11];                       // active-ray count per trace iteration
__device__ int g_tlist[11][NRAYS];               // active-ray lists per trace iteration
__device__ int g_scnt;                           // secant ray count
__device__ int g_slist[NRAYS];                   // secant ray indices
__device__ float g_szl[NRAYS], g_szh[NRAYS], g_ssl[NRAYS], g_ssh[NRAYS];

// Exact XLA-style elementwise ops: separate RN mul/add (no FMA contraction).
#define MUL(a, b) __fmul_rn((a), (b))
#define ADD(a, b) __fadd_rn((a), (b))
#define SUB(a, b) __fsub_rn((a), (b))

// Packed f32x2 ops (sm_100+). Each half rounds exactly like scalar IEEE FMA.
#define FMA2(acc, a, b) \
    asm("fma.rn.f32x2 %0, %1, %2, %0;" : "+l"(acc) : "l"(a), "l"(b))
#define PACK2(d, s) \
    asm("mov.b64 %0, {%1, %1};" : "=l"(d) : "r"(s))
#define UNPACK2(lo, hi, v) \
    asm("mov.b64 {%0, %1}, %2;" : "=r"(lo), "=r"(hi) : "l"(v))

// ---------------- shared weight cache ----------------
struct __align__(16) SdfShared {
    float4 W1p[64];     // {W1x[k], W1y[k], W1z[k], c1[k]}
    float b2[64];
    float W3[64];
    float W2[64 * 64];  // row-major [k][j]
    float cam[3];
    float b3;
};

__device__ __forceinline__ float softplusf(float x) {
    return ADD(fmaxf(x, 0.0f), __logf(__fadd_rn(1.0f, __expf(-fabsf(x)))));
}

__device__ __forceinline__ void load_shared(SdfShared* sh, const float* W1, const float* W2,
                                            const float* b2, const float* W3, const float* b3,
                                            const float* cam) {
    int t = threadIdx.x, nt = blockDim.x;
    for (int i = t; i < 64 * 64; i += nt) sh->W2[i] = W2[i];
    for (int i = t; i < 64; i += nt) {
        sh->W1p[i] = make_float4(W1[i], W1[64 + i], W1[128 + i], g_c1[i]);
        sh->b2[i] = b2[i];
        sh->W3[i] = W3[i];
    }
    if (t == 0) {
        sh->b3 = b3[0];
        sh->cam[0] = cam[0]; sh->cam[1] = cam[1]; sh->cam[2] = cam[2];
    }
    __syncthreads();
}

// Single-sample SDF eval. Layer-2 in packed f32x2 FMA (bit-identical to scalar).
__device__ __noinline__ float sdf_eval(const SdfShared* __restrict__ sh,
                                       float x, float y, float z) {
    unsigned long long acc2[32];
#pragma unroll
    for (int m = 0; m < 32; ++m) acc2[m] = 0ull;
#pragma unroll 8
    for (int k = 0; k < 64; ++k) {
        float4 w1 = sh->W1p[k];
        float pre = w1.w;
        pre = fmaf(x, w1.x, pre);
        pre = fmaf(y, w1.y, pre);
        pre = fmaf(z, w1.z, pre);
        float hk = softplusf(pre);
        unsigned long long hk2;
        PACK2(hk2, __float_as_uint(hk));
        const ulonglong2* wrow = (const ulonglong2*)(sh->W2) + k * 16;
#pragma unroll
        for (int j = 0; j < 16; ++j) {
            ulonglong2 wv = wrow[j];
            FMA2(acc2[2 * j + 0], hk2, wv.x);
            FMA2(acc2[2 * j + 1], hk2, wv.y);
        }
    }
    float d0 = 0.f, d1 = 0.f, d2 = 0.f, d3 = 0.f;
#pragma unroll
    for (int m = 0; m < 32; m += 2) {
        unsigned l0, h0, l1, h1;
        UNPACK2(l0, h0, acc2[m]);
        UNPACK2(l1, h1, acc2[m + 1]);
        int j = 2 * m;
        d0 = fmaf(softplusf(ADD(__uint_as_float(l0), sh->b2[j + 0])), sh->W3[j + 0], d0);
        d1 = fmaf(softplusf(ADD(__uint_as_float(h0), sh->b2[j + 1])), sh->W3[j + 1], d1);
        d2 = fmaf(softplusf(ADD(__uint_as_float(l1), sh->b2[j + 2])), sh->W3[j + 2], d2);
        d3 = fmaf(softplusf(ADD(__uint_as_float(h1), sh->b2[j + 3])), sh->W3[j + 3], d3);
    }
    float delta = ADD(((d0 + d1) + (d2 + d3)), sh->b3);
    float r2 = ADD(ADD(ADD(MUL(x, x), MUL(y, y)), MUL(z, z)), 1e-12f);
    return ADD(SUB(sqrtf(r2), 0.5f), MUL(0.05f, tanhf(delta)));
}

// Two-sample SDF eval (sample kernel): amortizes weight loads over two evals.
__device__ __noinline__ void sdf_eval2(const SdfShared* __restrict__ sh,
                                       float xa, float ya, float za,
                                       float xb, float yb, float zb,
                                       float* __restrict__ oa, float* __restrict__ ob) {
    unsigned long long accA[32], accB[32];
#pragma unroll
    for (int m = 0; m < 32; ++m) { accA[m] = 0ull; accB[m] = 0ull; }
#pragma unroll 2
    for (int k = 0; k < 64; ++k) {
        float4 w1 = sh->W1p[k];
        float preA = w1.w, preB = w1.w;
        preA = fmaf(xa, w1.x, preA);  preB = fmaf(xb, w1.x, preB);
        preA = fmaf(ya, w1.y, preA);  preB = fmaf(yb, w1.y, preB);
        preA = fmaf(za, w1.z, preA);  preB = fmaf(zb, w1.z, preB);
        float hA = softplusf(preA), hB = softplusf(preB);
        unsigned long long hA2, hB2;
        PACK2(hA2, __float_as_uint(hA));
        PACK2(hB2, __float_as_uint(hB));
        const ulonglong2* wrow = (const ulonglong2*)(sh->W2) + k * 16;
#pragma unroll
        for (int j = 0; j < 16; ++j) {
            ulonglong2 wv = wrow[j];
            FMA2(accA[2 * j + 0], hA2, wv.x);
            FMA2(accA[2 * j + 1], hA2, wv.y);
            FMA2(accB[2 * j + 0], hB2, wv.x);
            FMA2(accB[2 * j + 1], hB2, wv.y);
        }
    }
    float a0 = 0.f, a1 = 0.f, a2 = 0.f, a3 = 0.f;
    float b0 = 0.f, b1 = 0.f, b2_ = 0.f, b3_ = 0.f;
#pragma unroll
    for (int m = 0; m < 32; m += 2) {
        unsigned l0, h0, l1, h1;
        int j = 2 * m;
        UNPACK2(l0, h0, accA[m]);
        UNPACK2(l1, h1, accA[m + 1]);
        a0 = fmaf(softplusf(ADD(__uint_as_float(l0), sh->b2[j + 0])), sh->W3[j + 0], a0);
        a1 = fmaf(softplusf(ADD(__uint_as_float(h0), sh->b2[j + 1])), sh->W3[j + 1], a1);
        a2 = fmaf(softplusf(ADD(__uint_as_float(l1), sh->b2[j + 2])), sh->W3[j + 2], a2);
        a3 = fmaf(softplusf(ADD(__uint_as_float(h1), sh->b2[j + 3])), sh->W3[j + 3], a3);
        UNPACK2(l0, h0, accB[m]);
        UNPACK2(l1, h1, accB[m + 1]);
        b0 = fmaf(softplusf(ADD(__uint_as_float(l0), sh->b2[j + 0])), sh->W3[j + 0], b0);
        b1 = fmaf(softplusf(ADD(__uint_as_float(h0), sh->b2[j + 1])), sh->W3[j + 1], b1);
        b2_ = fmaf(softplusf(ADD(__uint_as_float(l1), sh->b2[j + 2])), sh->W3[j + 2], b2_);
        b3_ = fmaf(softplusf(ADD(__uint_as_float(h1), sh->b2[j + 3])), sh->W3[j + 3], b3_);
    }
    float dA = ADD(((a0 + a1) + (a2 + a3)), sh->b3);
    float dB = ADD(((b0 + b1) + (b2_ + b3_)), sh->b3);
    float rA = ADD(ADD(ADD(MUL(xa, xa), MUL(ya, ya)), MUL(za, za)), 1e-12f);
    float rB = ADD(ADD(ADD(MUL(xb, xb), MUL(yb, yb)), MUL(zb, zb)), 1e-12f);
    *oa = ADD(SUB(sqrtf(rA), 0.5f), MUL(0.05f, tanhf(dA)));
    *ob = ADD(SUB(sqrtf(rB), 0.5f), MUL(0.05f, tanhf(dB)));
}

// One sphere-tracing iteration for chain c of ray r (bit-identical to R12/R13).
__device__ __forceinline__ void trace_step(const SdfShared* __restrict__ sh,
                                           float dx, float dy, float dz,
                                           float cx, float cy, float cz,
                                           int c, unsigned mask2,
                                           float& acc, float& next, bool& unfin) {
    bool adv = unfin && (next > STH);
    unfin = adv;
    float cs = adv ? fminf(next, 0.5f) : 0.0f;   // clip(-0.5,0.5): next > STH > 0
    float st = MUL(1.2f, cs);
    acc = c ? SUB(acc, st) : ADD(acc, st);
    next = unfin ? sdf_eval(sh, ADD(cx, MUL(acc, dx)), ADD(cy, MUL(acc, dy)),
                            ADD(cz, MUL(acc, dz)))
                 : 0.0f;
    if (next < 0.0f) {                           // line-search (1 iter, step=0.5)
        float ls = MUL(0.5f, cs);
        acc = c ? ADD(acc, ls) : SUB(acc, ls);
        next = sdf_eval(sh, ADD(cx, MUL(acc, dx)), ADD(cy, MUL(acc, dy)),
                        ADD(cz, MUL(acc, dz)));
    }
    float acc_o = __shfl_xor_sync(mask2, acc, 1);
    bool inside = c ? (acc_o < acc) : (acc < acc_o);
    unfin = unfin && inside;
}

// ---------------- phase 0: fold latents + reset counters + mask detect ----------------
__global__ void prep_detect_kernel(const float* __restrict__ W1, const float* __restrict__ b1,
                                   const float* __restrict__ idl, const float* __restrict__ expl,
                                   const unsigned int* __restrict__ m) {
    if (blockIdx.x == 0) {
        int j = threadIdx.x;
        if (j == 0) { g_count = 0; g_scnt = 0; }
        if (j < 11) g_tcnt[j] = 0;
        if (j < 64) {
            float c = b1[j];
#pragma unroll 8
            for (int k = 0; k < 32; ++k) c = fmaf(idl[k], W1[(3 + k) * 64 + j], c);
#pragma unroll 8
            for (int k = 0; k < 32; ++k) c = fmaf(expl[k], W1[(35 + k) * 64 + j], c);
            g_c1[j] = c;
        }
    } else {
        __shared__ int any_big, any_f1, any_other;
        if (threadIdx.x == 0) { any_big = 0; any_f1 = 0; any_other = 0; }
        __syncthreads();
        for (int i = threadIdx.x; i < NRAYS / 4; i += blockDim.x) {
            unsigned v = m[i];
            if (v > 1u) {
                any_big = 1;
                if (v == 0x3F800000u) any_f1 = 1;
                else any_other = 1;
            }
        }
        __syncthreads();
        if (threadIdx.x == 0) {
            int mode;
            if (!any_big) mode = 1;
            else if (any_f1 && !any_other) mode = 2;
            else mode = 0;
            g_mask_mode = mode;
        }
    }
}

// ---------------- phase 1a: init + iteration 0 fused (block 64 for residency) ----------------
__global__ void __launch_bounds__(64)
trace_init_kernel(const float* __restrict__ cam_loc, const float* __restrict__ dirs,
                  const float* __restrict__ W1, const float* __restrict__ W2,
                  const float* __restrict__ b2, const float* __restrict__ W3,
                  const float* __restrict__ b3) {
    __shared__ SdfShared sh;
    load_shared(&sh, W1, W2, b2, W3, b3, cam_loc);

    int gid = blockIdx.x * blockDim.x + threadIdx.x;
    int r = gid >> 1;
    int c = gid & 1;                 // 0 = start chain, 1 = end chain
    int lane = threadIdx.x & 31;
    unsigned mask2 = 0x3u << (lane & ~1);
    float dx = dirs[3 * r + 0], dy = dirs[3 * r + 1], dz = dirs[3 * r + 2];
    float cx = sh.cam[0], cy = sh.cam[1], cz = sh.cam[2];

    float rcd = ADD(ADD(MUL(dx, cx), MUL(dy, cy)), MUL(dz, cz));
    float cam2 = ADD(ADD(MUL(cx, cx), MUL(cy, cy)), MUL(cz, cz));
    float under = SUB(MUL(rcd, rcd), SUB(cam2, 1.0f));   // R = 1
    bool mask = under > 0.0f;
    float sq = sqrtf(mask ? under : 1.0f);
    float acc = mask ? fmaxf(SUB((c ? sq : -sq), rcd), 0.0f) : 0.0f;
    bool unfin = mask;

    float next = 0.0f;
    if (mask)
        next = sdf_eval(&sh, ADD(cx, MUL(acc, dx)), ADD(cy, MUL(acc, dy)), ADD(cz, MUL(acc, dz)));
    float next_o = __shfl_xor_sync(0xffffffffu, next, 1);
    bool no_int = (next < 0.0f) && (next_o < 0.0f);

    // iteration 0 (fused)
    trace_step(&sh, dx, dy, dz, cx, cy, cz, c, mask2, acc, next, unfin);

    if (c) { g_acc_e[r] = acc; g_next_e[r] = next; }
    else   { g_acc_s[r] = acc; g_next_s[r] = next; }
    unsigned ob = __shfl_xor_sync(mask2, (unsigned)unfin, 1);
    if (c == 0) {
        unsigned nb = (unfin ? 1u : 0u) | (ob ? 2u : 0u) | (no_int ? 4u : 0u);
        g_unfin[r] = nb;
        if (nb & 3u) {
            int pos = atomicAdd(&g_tcnt[1], 1);
            g_tlist[1][pos] = r;
        }
    }
}

// ---------------- phase 1b: fused ladder — iterations [a, b); block 64 ----------------
// When b == 10 (final), appends sampler rays (unfin_s && next_s > STH) to g_list.
__global__ void __launch_bounds__(64)
trace_ladder_kernel(const float* __restrict__ cam_loc, const float* __restrict__ dirs,
                    const float* __restrict__ W1, const float* __restrict__ W2,
                    const float* __restrict__ b2, const float* __restrict__ W3,
                    const float* __restrict__ b3, int a, int b) {
    int cnt = g_tcnt[a];
    if (blockIdx.x * 64 >= 2 * cnt) return;      // uniform per block

    __shared__ SdfShared sh;
    load_shared(&sh, W1, W2, b2, W3, b3, cam_loc);

    int t = blockIdx.x * 64 + threadIdx.x;
    if (t >= 2 * cnt) return;                    // pairs stay together (2*cnt even)
    int i = t >> 1;
    int c = t & 1;
    int lane = threadIdx.x & 31;
    unsigned mask2 = 0x3u << (lane & ~1);
    int r = g_tlist[a][i];

    float dx = dirs[3 * r + 0], dy = dirs[3 * r + 1], dz = dirs[3 * r + 2];
    float cx = sh.cam[0], cy = sh.cam[1], cz = sh.cam[2];

    float acc = c ? g_acc_e[r] : g_acc_s[r];
    float next = c ? g_next_e[r] : g_next_s[r];
    unsigned ub = g_unfin[r];
    bool unfin = (ub >> c) & 1u;

    for (int it = a; it < b; ++it)
        trace_step(&sh, dx, dy, dz, cx, cy, cz, c, mask2, acc, next, unfin);

    if (c) { g_acc_e[r] = acc; g_next_e[r] = next; }
    else   { g_acc_s[r] = acc; g_next_s[r] = next; }
    unsigned ob = __shfl_xor_sync(mask2, (unsigned)unfin, 1);
    if (c == 0) {
        unsigned nb = (unfin ? 1u : 0u) | (ob ? 2u : 0u) | (ub & 4u);
        g_unfin[r] = nb;
        if (b < 10) {
            if (nb & 3u) {
                int pos = atomicAdd(&g_tcnt[b], 1);
                g_tlist[b][pos] = r;
            }
        } else {
            // final: sampler = unfin_s after final threshold check (it==10)
            if (unfin && (next > STH)) {
                int pos = atomicAdd(&g_count, 1);
                g_list[pos] = r;
            }
        }
    }
}

// ---------------- phase 2: compacted sampler — two samples per thread; block 64 ----------------
__global__ void __launch_bounds__(64, 1)
sample_kernel(const float* __restrict__ cam_loc, const float* __restrict__ dirs,
              const float* __restrict__ W1, const float* __restrict__ W2,
              const float* __restrict__ b2, const float* __restrict__ W3,
              const float* __restrict__ b3) {
    int cnt = g_count;
    int nwork = 50 * cnt;
    if (blockIdx.x * 64 >= nwork) return;

    __shared__ SdfShared sh;
    load_shared(&sh, W1, W2, b2, W3, b3, cam_loc);

    int t = blockIdx.x * 64 + threadIdx.x;
    if (t >= nwork) return;
    int i = t / 50;
    int s = t - 50 * i;
    int r = g_list[i];

    float mn = g_acc_s[r], mx = g_acc_e[r];
    float dlt = SUB(mx, mn);
    float dx = dirs[3 * r + 0], dy = dirs[3 * r + 1], dz = dirs[3 * r + 2];

    float ta = MUL((float)s, 1.0f / 99.0f);
    float da = ADD(mn, MUL(ta, dlt));
    float xa = ADD(sh.cam[0], MUL(da, dx));
    float ya = ADD(sh.cam[1], MUL(da, dy));
    float za = ADD(sh.cam[2], MUL(da, dz));

    float tb = MUL((float)(s + 50), 1.0f / 99.0f);
    float db = ADD(mn, MUL(tb, dlt));
    float xb = ADD(sh.cam[0], MUL(db, dx));
    float yb = ADD(sh.cam[1], MUL(db, dy));
    float zb = ADD(sh.cam[2], MUL(db, dz));

    float va, vb;
    sdf_eval2(&sh, xa, ya, za, xb, yb, zb, &va, &vb);
    g_sdfval[s * NRAYS + r] = va;
    g_sdfval[(s + 50) * NRAYS + r] = vb;
}

// ---------------- phase 3a: flags + argmins + provisional outputs + secant compaction ----------------
__global__ void finish_a_kernel(const float* __restrict__ cam_loc, const float* __restrict__ dirs,
                                const void* __restrict__ objmask, float* __restrict__ out) {
    int r = blockIdx.x * blockDim.x + threadIdx.x;
    unsigned ub = g_unfin[r];
    float acc_s = g_acc_s[r];
    float acc_e = g_acc_e[r];
    bool sampler = (ub & 1u) && (g_next_s[r] > STH);
    bool netobj = (acc_s < acc_e) && !(ub & 4u);

    float dx = dirs[3 * r + 0], dy = dirs[3 * r + 1], dz = dirs[3 * r + 2];
    float cx = cam_loc[0], cy = cam_loc[1], cz = cam_loc[2];

    float out_d, out_m;
    if (!sampler) {
        out_d = acc_s;
        out_m = netobj ? 1.0f : 0.0f;
    } else {
        float mn = acc_s, mx = acc_e;
        float dlt = SUB(mx, mn);
        float best1 = 1e30f; int ind = 0;
        float best2 = 1e30f; int ind_out = 0;
        for (int s = 0; s < NSTEPS; ++s) {
            float v = g_sdfval[s * NRAYS + r];
            float sg = (v > 0.f) ? 1.f : ((v < 0.f) ? -1.f : 0.f);
            float m1 = sg * (float)(NSTEPS - s);
            if (m1 < best1) { best1 = m1; ind = s; }
            if (v < best2) { best2 = v; ind_out = s; }
        }
        float d_at = ADD(mn, MUL(MUL((float)ind, 1.f / 99.f), dlt));
        float sdf_at = g_sdfval[ind * NRAYS + r];
        bool net_surf = sdf_at < 0.f;
        int mode = g_mask_mode;
        bool obj = (mode == 1) ? (((const int*)objmask)[r] != 0)
                 : (mode == 2) ? (((const float*)objmask)[r] != 0.0f)
                               : (((const unsigned char*)objmask)[r] != 0);
        bool p_out = !(obj && net_surf);
        if (p_out) {
            out_d = ADD(mn, MUL(MUL((float)ind_out, 1.f / 99.f), dlt));
        } else {
            int ind_lo = (ind == 0) ? (NSTEPS - 1) : (ind - 1);
            int pos = atomicAdd(&g_scnt, 1);
            g_slist[pos] = r;
            g_szh[pos] = d_at;
            g_ssh[pos] = sdf_at;
            g_szl[pos] = ADD(mn, MUL(MUL((float)ind_lo, 1.f / 99.f), dlt));
            g_ssl[pos] = g_sdfval[ind_lo * NRAYS + r];
            out_d = d_at;
        }
        out_m = net_surf ? 1.0f : 0.0f;
    }

    out[3 * r + 0] = ADD(cx, MUL(out_d, dx));
    out[3 * r + 1] = ADD(cy, MUL(out_d, dy));
    out[3 * r + 2] = ADD(cz, MUL(out_d, dz));
    out[3 * NRAYS + r] = out_m;
    out[4 * NRAYS + r] = out_d;
}

// ---------------- phase 3b: compacted secant refinement; block 64 ----------------
__global__ void __launch_bounds__(64, 1)
finish_b_kernel(const float* __restrict__ cam_loc, const float* __restrict__ dirs,
                const float* __restrict__ W1, const float* __restrict__ W2,
                const float* __restrict__ b2, const float* __restrict__ W3,
                const float* __restrict__ b3, float* __restrict__ out) {
    int cnt = g_scnt;
    if (blockIdx.x * 64 >= cnt) return;

    __shared__ SdfShared sh;
    load_shared(&sh, W1, W2, b2, W3, b3, cam_loc);

    int t = blockIdx.x * 64 + threadIdx.x;
    if (t >= cnt) return;
    int r = g_slist[t];
    float dx = dirs[3 * r + 0], dy = dirs[3 * r + 1], dz = dirs[3 * r + 2];
    float cx = sh.cam[0], cy = sh.cam[1], cz = sh.cam[2];

    float z_low = g_szl[t], z_high = g_szh[t];
    float sdf_low = g_ssl[t], sdf_high = g_ssh[t];
    float denom = SUB(sdf_high, sdf_low);
    float z_pred = ADD(__fdiv_rn(MUL(-sdf_low, SUB(z_high, z_low)),
                                 (denom == 0.f) ? 1.f : denom), z_low);
    for (int i = 0; i < 8; ++i) {
        float sm = sdf_eval(&sh, ADD(cx, MUL(z_pred, dx)), ADD(cy, MUL(z_pred, dy)),
                            ADD(cz, MUL(z_pred, dz)));
        if (sm > 0.f) { z_low = z_pred; sdf_low = sm; }
        if (sm < 0.f) { z_high = z_pred; sdf_high = sm; }
        denom = SUB(sdf_high, sdf_low);
        z_pred = ADD(__fdiv_rn(MUL(-sdf_low, SUB(z_high, z_low)),
                               (denom == 0.f) ? 1.f : denom), z_low);
    }
    out[3 * r + 0] = ADD(cx, MUL(z_pred, dx));
    out[3 * r + 1] = ADD(cy, MUL(z_pred, dy));
    out[3 * r + 2] = ADD(cz, MUL(z_pred, dz));
    out[4 * NRAYS + r] = z_pred;               // out_m already correct (net_surf=1)
}

extern "C" void kernel_launch(void* const* d_in, const int* in_sizes, int n_in,
                              void* d_out, int out_size) {
    const float* cam   = (const float*)d_in[0];
    const void*  omask = d_in[1];
    const float* dirs  = (const float*)d_in[2];
    const float* idl   = (const float*)d_in[3];
    const float* expl  = (const float*)d_in[4];
    const float* W1    = (const float*)d_in[5];
    const float* b1    = (const float*)d_in[6];
    const float* W2    = (const float*)d_in[7];
    const float* b2    = (const float*)d_in[8];
    const float* W3    = (const float*)d_in[9];
    const float* b3    = (const float*)d_in[10];
    float* out = (float*)d_out;

    prep_detect_kernel<<<2, 256>>>(W1, b1, idl, expl, (const unsigned int*)omask);
    trace_init_kernel<<<(2 * NRAYS) / 64, 64>>>(cam, dirs, W1, W2, b2, W3, b3);
    trace_ladder_kernel<<<(2 * NRAYS) / 64, 64>>>(cam, dirs, W1, W2, b2, W3, b3, 1, 3);
    trace_ladder_kernel<<<(2 * NRAYS) / 64, 64>>>(cam, dirs, W1, W2, b2, W3, b3, 3, 5);
    trace_ladder_kernel<<<(2 * NRAYS) / 64, 64>>>(cam, dirs, W1, W2, b2, W3, b3, 5, 7);
    trace_ladder_kernel<<<(2 * NRAYS) / 64, 64>>>(cam, dirs, W1, W2, b2, W3, b3, 7, 9);
    trace_ladder_kernel<<<(2 * NRAYS) / 64, 64>>>(cam, dirs, W1, W2, b2, W3, b3, 9, 10);
    sample_kernel<<<(50 * NRAYS) / 64, 64>>>(cam, dirs, W1, W2, b2, W3, b3);
    finish_a_kernel<<<NRAYS / 256, 256>>>(cam, dirs, omask, out);
    finish_b_kernel<<<NRAYS / 64, 64>>>(cam, dirs, W1, W2, b2, W3, b3, out);
}

// round 17
// speedup vs baseline: 1.4312x; 1.0108x over previous
#include <cuda_runtime.h>

#define NRAYS 16384
#define NSTEPS 100
#define STH 5e-5f

// ---------------- device scratch (no allocations allowed) ----------------
__device__ float g_c1[64];
__device__ float g_acc_s[NRAYS];
__device__ float g_acc_e[NRAYS];
__device__ float g_next_s[NRAYS];
__device__ float g_next_e[NRAYS];
__device__ unsigned char g_unfin[NRAYS];         // bit0 unfin_s, bit1 unfin_e, bit2 no_int
__device__ float g_sdfval[NSTEPS * NRAYS];       // sample-major: [s*NRAYS + r]
__device__ int g_mask_mode;                      // 0=bytes, 1=int32 words, 2=float32 words
__device__ int g_count;                          // number of sampler rays
__device__ int g_list[NRAYS];                    // compacted sampler-ray indices
__device__ int g_tcnt[11];                       // active-ray count per trace iteration
__device__ int g_tlist[11][NRAYS];               // active-ray lists per trace iteration
__device__ int g_scnt;                           // secant ray count
__device__ int g_slist[NRAYS];                   // secant ray indices
__device__ float g_szl[NRAYS], g_szh[NRAYS], g_ssl[NRAYS], g_ssh[NRAYS];

// Exact XLA-style elementwise ops: separate RN mul/add (no FMA contraction).
#define MUL(a, b) __fmul_rn((a), (b))
#define ADD(a, b) __fadd_rn((a), (b))
#define SUB(a, b) __fsub_rn((a), (b))

// Packed f32x2 ops (sm_100+). Each half rounds exactly like scalar IEEE FMA.
#define FMA2(acc, a, b) \
    asm("fma.rn.f32x2 %0, %1, %2, %0;" : "+l"(acc) : "l"(a), "l"(b))
#define PACK2(d, s) \
    asm("mov.b64 %0, {%1, %1};" : "=l"(d) : "r"(s))
#define UNPACK2(lo, hi, v) \
    asm("mov.b64 {%0, %1}, %2;" : "=r"(lo), "=r"(hi) : "l"(v))

// ---------------- shared weight cache ----------------
struct __align__(16) SdfShared {
    float4 W1p[64];     // {W1x[k], W1y[k], W1z[k], c1[k]}
    float b2[64];
    float W3[64];
    float W2[64 * 64];  // row-major [k][j]
    float cam[3];
    float b3;
};

__device__ __forceinline__ float softplusf(float x) {
    return ADD(fmaxf(x, 0.0f), __logf(__fadd_rn(1.0f, __expf(-fabsf(x)))));
}

__device__ __forceinline__ void load_shared(SdfShared* sh, const float* W1, const float* W2,
                                            const float* b2, const float* W3, const float* b3,
                                            const float* cam) {
    int t = threadIdx.x, nt = blockDim.x;
    for (int i = t; i < 64 * 64; i += nt) sh->W2[i] = W2[i];
    for (int i = t; i < 64; i += nt) {
        sh->W1p[i] = make_float4(W1[i], W1[64 + i], W1[128 + i], g_c1[i]);
        sh->b2[i] = b2[i];
        sh->W3[i] = W3[i];
    }
    if (t == 0) {
        sh->b3 = b3[0];
        sh->cam[0] = cam[0]; sh->cam[1] = cam[1]; sh->cam[2] = cam[2];
    }
    __syncthreads();
}

// Single-sample SDF eval. Layer-2 in packed f32x2 FMA (bit-identical to scalar).
__device__ __noinline__ float sdf_eval(const SdfShared* __restrict__ sh,
                                       float x, float y, float z) {
    unsigned long long acc2[32];
#pragma unroll
    for (int m = 0; m < 32; ++m) acc2[m] = 0ull;
#pragma unroll 8
    for (int k = 0; k < 64; ++k) {
        float4 w1 = sh->W1p[k];
        float pre = w1.w;
        pre = fmaf(x, w1.x, pre);
        pre = fmaf(y, w1.y, pre);
        pre = fmaf(z, w1.z, pre);
        float hk = softplusf(pre);
        unsigned long long hk2;
        PACK2(hk2, __float_as_uint(hk));
        const ulonglong2* wrow = (const ulonglong2*)(sh->W2) + k * 16;
#pragma unroll
        for (int j = 0; j < 16; ++j) {
            ulonglong2 wv = wrow[j];
            FMA2(acc2[2 * j + 0], hk2, wv.x);
            FMA2(acc2[2 * j + 1], hk2, wv.y);
        }
    }
    float d0 = 0.f, d1 = 0.f, d2 = 0.f, d3 = 0.f;
#pragma unroll
    for (int m = 0; m < 32; m += 2) {
        unsigned l0, h0, l1, h1;
        UNPACK2(l0, h0, acc2[m]);
        UNPACK2(l1, h1, acc2[m + 1]);
        int j = 2 * m;
        d0 = fmaf(softplusf(ADD(__uint_as_float(l0), sh->b2[j + 0])), sh->W3[j + 0], d0);
        d1 = fmaf(softplusf(ADD(__uint_as_float(h0), sh->b2[j + 1])), sh->W3[j + 1], d1);
        d2 = fmaf(softplusf(ADD(__uint_as_float(l1), sh->b2[j + 2])), sh->W3[j + 2], d2);
        d3 = fmaf(softplusf(ADD(__uint_as_float(h1), sh->b2[j + 3])), sh->W3[j + 3], d3);
    }
    float delta = ADD(((d0 + d1) + (d2 + d3)), sh->b3);
    float r2 = ADD(ADD(ADD(MUL(x, x), MUL(y, y)), MUL(z, z)), 1e-12f);
    return ADD(SUB(sqrtf(r2), 0.5f), MUL(0.05f, tanhf(delta)));
}

// Two-sample SDF eval (sample kernel): amortizes weight loads over two evals.
__device__ __noinline__ void sdf_eval2(const SdfShared* __restrict__ sh,
                                       float xa, float ya, float za,
                                       float xb, float yb, float zb,
                                       float* __restrict__ oa, float* __restrict__ ob) {
    unsigned long long accA[32], accB[32];
#pragma unroll
    for (int m = 0; m < 32; ++m) { accA[m] = 0ull; accB[m] = 0ull; }
#pragma unroll 2
    for (int k = 0; k < 64; ++k) {
        float4 w1 = sh->W1p[k];
        float preA = w1.w, preB = w1.w;
        preA = fmaf(xa, w1.x, preA);  preB = fmaf(xb, w1.x, preB);
        preA = fmaf(ya, w1.y, preA);  preB = fmaf(yb, w1.y, preB);
        preA = fmaf(za, w1.z, preA);  preB = fmaf(zb, w1.z, preB);
        float hA = softplusf(preA), hB = softplusf(preB);
        unsigned long long hA2, hB2;
        PACK2(hA2, __float_as_uint(hA));
        PACK2(hB2, __float_as_uint(hB));
        const ulonglong2* wrow = (const ulonglong2*)(sh->W2) + k * 16;
#pragma unroll
        for (int j = 0; j < 16; ++j) {
            ulonglong2 wv = wrow[j];
            FMA2(accA[2 * j + 0], hA2, wv.x);
            FMA2(accA[2 * j + 1], hA2, wv.y);
            FMA2(accB[2 * j + 0], hB2, wv.x);
            FMA2(accB[2 * j + 1], hB2, wv.y);
        }
    }
    float a0 = 0.f, a1 = 0.f, a2 = 0.f, a3 = 0.f;
    float b0 = 0.f, b1 = 0.f, b2_ = 0.f, b3_ = 0.f;
#pragma unroll
    for (int m = 0; m < 32; m += 2) {
        unsigned l0, h0, l1, h1;
        int j = 2 * m;
        UNPACK2(l0, h0, accA[m]);
        UNPACK2(l1, h1, accA[m + 1]);
        a0 = fmaf(softplusf(ADD(__uint_as_float(l0), sh->b2[j + 0])), sh->W3[j + 0], a0);
        a1 = fmaf(softplusf(ADD(__uint_as_float(h0), sh->b2[j + 1])), sh->W3[j + 1], a1);
        a2 = fmaf(softplusf(ADD(__uint_as_float(l1), sh->b2[j + 2])), sh->W3[j + 2], a2);
        a3 = fmaf(softplusf(ADD(__uint_as_float(h1), sh->b2[j + 3])), sh->W3[j + 3], a3);
        UNPACK2(l0, h0, accB[m]);
        UNPACK2(l1, h1, accB[m + 1]);
        b0 = fmaf(softplusf(ADD(__uint_as_float(l0), sh->b2[j + 0])), sh->W3[j + 0], b0);
        b1 = fmaf(softplusf(ADD(__uint_as_float(h0), sh->b2[j + 1])), sh->W3[j + 1], b1);
        b2_ = fmaf(softplusf(ADD(__uint_as_float(l1), sh->b2[j + 2])), sh->W3[j + 2], b2_);
        b3_ = fmaf(softplusf(ADD(__uint_as_float(h1), sh->b2[j + 3])), sh->W3[j + 3], b3_);
    }
    float dA = ADD(((a0 + a1) + (a2 + a3)), sh->b3);
    float dB = ADD(((b0 + b1) + (b2_ + b3_)), sh->b3);
    float rA = ADD(ADD(ADD(MUL(xa, xa), MUL(ya, ya)), MUL(za, za)), 1e-12f);
    float rB = ADD(ADD(ADD(MUL(xb, xb), MUL(yb, yb)), MUL(zb, zb)), 1e-12f);
    *oa = ADD(SUB(sqrtf(rA), 0.5f), MUL(0.05f, tanhf(dA)));
    *ob = ADD(SUB(sqrtf(rB), 0.5f), MUL(0.05f, tanhf(dB)));
}

// One sphere-tracing iteration for chain c of ray r (bit-identical to R12/R13).
__device__ __forceinline__ void trace_step(const SdfShared* __restrict__ sh,
                                           float dx, float dy, float dz,
                                           float cx, float cy, float cz,
                                           int c, unsigned mask2,
                                           float& acc, float& next, bool& unfin) {
    bool adv = unfin && (next > STH);
    unfin = adv;
    float cs = adv ? fminf(next, 0.5f) : 0.0f;   // clip(-0.5,0.5): next > STH > 0
    float st = MUL(1.2f, cs);
    acc = c ? SUB(acc, st) : ADD(acc, st);
    next = unfin ? sdf_eval(sh, ADD(cx, MUL(acc, dx)), ADD(cy, MUL(acc, dy)),
                            ADD(cz, MUL(acc, dz)))
                 : 0.0f;
    if (next < 0.0f) {                           // line-search (1 iter, step=0.5)
        float ls = MUL(0.5f, cs);
        acc = c ? ADD(acc, ls) : SUB(acc, ls);
        next = sdf_eval(sh, ADD(cx, MUL(acc, dx)), ADD(cy, MUL(acc, dy)),
                        ADD(cz, MUL(acc, dz)));
    }
    float acc_o = __shfl_xor_sync(mask2, acc, 1);
    bool inside = c ? (acc_o < acc) : (acc < acc_o);
    unfin = unfin && inside;
}

// ---------------- phase 0: fold latents + reset counters + mask detect ----------------
__global__ void prep_detect_kernel(const float* __restrict__ W1, const float* __restrict__ b1,
                                   const float* __restrict__ idl, const float* __restrict__ expl,
                                   const unsigned int* __restrict__ m) {
    if (blockIdx.x == 0) {
        int j = threadIdx.x;
        if (j == 0) { g_count = 0; g_scnt = 0; }
        if (j < 11) g_tcnt[j] = 0;
        if (j < 64) {
            float c = b1[j];
#pragma unroll 8
            for (int k = 0; k < 32; ++k) c = fmaf(idl[k], W1[(3 + k) * 64 + j], c);
#pragma unroll 8
            for (int k = 0; k < 32; ++k) c = fmaf(expl[k], W1[(35 + k) * 64 + j], c);
            g_c1[j] = c;
        }
    } else {
        __shared__ int any_big, any_f1, any_other;
        if (threadIdx.x == 0) { any_big = 0; any_f1 = 0; any_other = 0; }
        __syncthreads();
        for (int i = threadIdx.x; i < NRAYS / 4; i += blockDim.x) {
            unsigned v = m[i];
            if (v > 1u) {
                any_big = 1;
                if (v == 0x3F800000u) any_f1 = 1;
                else any_other = 1;
            }
        }
        __syncthreads();
        if (threadIdx.x == 0) {
            int mode;
            if (!any_big) mode = 1;
            else if (any_f1 && !any_other) mode = 2;
            else mode = 0;
            g_mask_mode = mode;
        }
    }
}

// ---------------- phase 1a: init + iteration 0 fused (block 128: full-grid kernel) ----------------
__global__ void __launch_bounds__(128)
trace_init_kernel(const float* __restrict__ cam_loc, const float* __restrict__ dirs,
                  const float* __restrict__ W1, const float* __restrict__ W2,
                  const float* __restrict__ b2, const float* __restrict__ W3,
                  const float* __restrict__ b3) {
    __shared__ SdfShared sh;
    load_shared(&sh, W1, W2, b2, W3, b3, cam_loc);

    int gid = blockIdx.x * blockDim.x + threadIdx.x;
    int r = gid >> 1;
    int c = gid & 1;                 // 0 = start chain, 1 = end chain
    int lane = threadIdx.x & 31;
    unsigned mask2 = 0x3u << (lane & ~1);
    float dx = dirs[3 * r + 0], dy = dirs[3 * r + 1], dz = dirs[3 * r + 2];
    float cx = sh.cam[0], cy = sh.cam[1], cz = sh.cam[2];

    float rcd = ADD(ADD(MUL(dx, cx), MUL(dy, cy)), MUL(dz, cz));
    float cam2 = ADD(ADD(MUL(cx, cx), MUL(cy, cy)), MUL(cz, cz));
    float under = SUB(MUL(rcd, rcd), SUB(cam2, 1.0f));   // R = 1
    bool mask = under > 0.0f;
    float sq = sqrtf(mask ? under : 1.0f);
    float acc = mask ? fmaxf(SUB((c ? sq : -sq), rcd), 0.0f) : 0.0f;
    bool unfin = mask;

    float next = 0.0f;
    if (mask)
        next = sdf_eval(&sh, ADD(cx, MUL(acc, dx)), ADD(cy, MUL(acc, dy)), ADD(cz, MUL(acc, dz)));
    float next_o = __shfl_xor_sync(0xffffffffu, next, 1);
    bool no_int = (next < 0.0f) && (next_o < 0.0f);

    // iteration 0 (fused)
    trace_step(&sh, dx, dy, dz, cx, cy, cz, c, mask2, acc, next, unfin);

    if (c) { g_acc_e[r] = acc; g_next_e[r] = next; }
    else   { g_acc_s[r] = acc; g_next_s[r] = next; }
    unsigned ob = __shfl_xor_sync(mask2, (unsigned)unfin, 1);
    if (c == 0) {
        unsigned nb = (unfin ? 1u : 0u) | (ob ? 2u : 0u) | (no_int ? 4u : 0u);
        g_unfin[r] = nb;
        if (nb & 3u) {
            int pos = atomicAdd(&g_tcnt[1], 1);
            g_tlist[1][pos] = r;
        }
    }
}

// ---------------- phase 1b: fused ladder — iterations [a, b); block 64 (compacted lists) ----------------
// When b == 10 (final), appends sampler rays (unfin_s && next_s > STH) to g_list.
__global__ void __launch_bounds__(64)
trace_ladder_kernel(const float* __restrict__ cam_loc, const float* __restrict__ dirs,
                    const float* __restrict__ W1, const float* __restrict__ W2,
                    const float* __restrict__ b2, const float* __restrict__ W3,
                    const float* __restrict__ b3, int a, int b) {
    int cnt = g_tcnt[a];
    if (blockIdx.x * 64 >= 2 * cnt) return;      // uniform per block

    __shared__ SdfShared sh;
    load_shared(&sh, W1, W2, b2, W3, b3, cam_loc);

    int t = blockIdx.x * 64 + threadIdx.x;
    if (t >= 2 * cnt) return;                    // pairs stay together (2*cnt even)
    int i = t >> 1;
    int c = t & 1;
    int lane = threadIdx.x & 31;
    unsigned mask2 = 0x3u << (lane & ~1);
    int r = g_tlist[a][i];

    float dx = dirs[3 * r + 0], dy = dirs[3 * r + 1], dz = dirs[3 * r + 2];
    float cx = sh.cam[0], cy = sh.cam[1], cz = sh.cam[2];

    float acc = c ? g_acc_e[r] : g_acc_s[r];
    float next = c ? g_next_e[r] : g_next_s[r];
    unsigned ub = g_unfin[r];
    bool unfin = (ub >> c) & 1u;

    for (int it = a; it < b; ++it)
        trace_step(&sh, dx, dy, dz, cx, cy, cz, c, mask2, acc, next, unfin);

    if (c) { g_acc_e[r] = acc; g_next_e[r] = next; }
    else   { g_acc_s[r] = acc; g_next_s[r] = next; }
    unsigned ob = __shfl_xor_sync(mask2, (unsigned)unfin, 1);
    if (c == 0) {
        unsigned nb = (unfin ? 1u : 0u) | (ob ? 2u : 0u) | (ub & 4u);
        g_unfin[r] = nb;
        if (b < 10) {
            if (nb & 3u) {
                int pos = atomicAdd(&g_tcnt[b], 1);
                g_tlist[b][pos] = r;
            }
        } else {
            // final: sampler = unfin_s after final threshold check (it==10)
            if (unfin && (next > STH)) {
                int pos = atomicAdd(&g_count, 1);
                g_list[pos] = r;
            }
        }
    }
}

// ---------------- phase 2: compacted sampler — two samples per thread; block 128 ----------------
__global__ void __launch_bounds__(128, 1)
sample_kernel(const float* __restrict__ cam_loc, const float* __restrict__ dirs,
              const float* __restrict__ W1, const float* __restrict__ W2,
              const float* __restrict__ b2, const float* __restrict__ W3,
              const float* __restrict__ b3) {
    int cnt = g_count;
    int nwork = 50 * cnt;
    if (blockIdx.x * 128 >= nwork) return;

    __shared__ SdfShared sh;
    load_shared(&sh, W1, W2, b2, W3, b3, cam_loc);

    int t = blockIdx.x * 128 + threadIdx.x;
    if (t >= nwork) return;
    int i = t / 50;
    int s = t - 50 * i;
    int r = g_list[i];

    float mn = g_acc_s[r], mx = g_acc_e[r];
    float dlt = SUB(mx, mn);
    float dx = dirs[3 * r + 0], dy = dirs[3 * r + 1], dz = dirs[3 * r + 2];

    float ta = MUL((float)s, 1.0f / 99.0f);
    float da = ADD(mn, MUL(ta, dlt));
    float xa = ADD(sh.cam[0], MUL(da, dx));
    float ya = ADD(sh.cam[1], MUL(da, dy));
    float za = ADD(sh.cam[2], MUL(da, dz));

    float tb = MUL((float)(s + 50), 1.0f / 99.0f);
    float db = ADD(mn, MUL(tb, dlt));
    float xb = ADD(sh.cam[0], MUL(db, dx));
    float yb = ADD(sh.cam[1], MUL(db, dy));
    float zb = ADD(sh.cam[2], MUL(db, dz));

    float va, vb;
    sdf_eval2(&sh, xa, ya, za, xb, yb, zb, &va, &vb);
    g_sdfval[s * NRAYS + r] = va;
    g_sdfval[(s + 50) * NRAYS + r] = vb;
}

// ---------------- phase 3a: flags + argmins + provisional outputs + secant compaction ----------------
__global__ void finish_a_kernel(const float* __restrict__ cam_loc, const float* __restrict__ dirs,
                                const void* __restrict__ objmask, float* __restrict__ out) {
    int r = blockIdx.x * blockDim.x + threadIdx.x;
    unsigned ub = g_unfin[r];
    float acc_s = g_acc_s[r];
    float acc_e = g_acc_e[r];
    bool sampler = (ub & 1u) && (g_next_s[r] > STH);
    bool netobj = (acc_s < acc_e) && !(ub & 4u);

    float dx = dirs[3 * r + 0], dy = dirs[3 * r + 1], dz = dirs[3 * r + 2];
    float cx = cam_loc[0], cy = cam_loc[1], cz = cam_loc[2];

    float out_d, out_m;
    if (!sampler) {
        out_d = acc_s;
        out_m = netobj ? 1.0f : 0.0f;
    } else {
        float mn = acc_s, mx = acc_e;
        float dlt = SUB(mx, mn);
        float best1 = 1e30f; int ind = 0;
        float best2 = 1e30f; int ind_out = 0;
        for (int s = 0; s < NSTEPS; ++s) {
            float v = g_sdfval[s * NRAYS + r];
            float sg = (v > 0.f) ? 1.f : ((v < 0.f) ? -1.f : 0.f);
            float m1 = sg * (float)(NSTEPS - s);
            if (m1 < best1) { best1 = m1; ind = s; }
            if (v < best2) { best2 = v; ind_out = s; }
        }
        float d_at = ADD(mn, MUL(MUL((float)ind, 1.f / 99.f), dlt));
        float sdf_at = g_sdfval[ind * NRAYS + r];
        bool net_surf = sdf_at < 0.f;
        int mode = g_mask_mode;
        bool obj = (mode == 1) ? (((const int*)objmask)[r] != 0)
                 : (mode == 2) ? (((const float*)objmask)[r] != 0.0f)
                               : (((const unsigned char*)objmask)[r] != 0);
        bool p_out = !(obj && net_surf);
        if (p_out) {
            out_d = ADD(mn, MUL(MUL((float)ind_out, 1.f / 99.f), dlt));
        } else {
            int ind_lo = (ind == 0) ? (NSTEPS - 1) : (ind - 1);
            int pos = atomicAdd(&g_scnt, 1);
            g_slist[pos] = r;
            g_szh[pos] = d_at;
            g_ssh[pos] = sdf_at;
            g_szl[pos] = ADD(mn, MUL(MUL((float)ind_lo, 1.f / 99.f), dlt));
            g_ssl[pos] = g_sdfval[ind_lo * NRAYS + r];
            out_d = d_at;
        }
        out_m = net_surf ? 1.0f : 0.0f;
    }

    out[3 * r + 0] = ADD(cx, MUL(out_d, dx));
    out[3 * r + 1] = ADD(cy, MUL(out_d, dy));
    out[3 * r + 2] = ADD(cz, MUL(out_d, dz));
    out[3 * NRAYS + r] = out_m;
    out[4 * NRAYS + r] = out_d;
}

// ---------------- phase 3b: compacted secant refinement; block 64 ----------------
__global__ void __launch_bounds__(64, 1)
finish_b_kernel(const float* __restrict__ cam_loc, const float* __restrict__ dirs,
                const float* __restrict__ W1, const float* __restrict__ W2,
                const float* __restrict__ b2, const float* __restrict__ W3,
                const float* __restrict__ b3, float* __restrict__ out) {
    int cnt = g_scnt;
    if (blockIdx.x * 64 >= cnt) return;

    __shared__ SdfShared sh;
    load_shared(&sh, W1, W2, b2, W3, b3, cam_loc);

    int t = blockIdx.x * 64 + threadIdx.x;
    if (t >= cnt) return;
    int r = g_slist[t];
    float dx = dirs[3 * r + 0], dy = dirs[3 * r + 1], dz = dirs[3 * r + 2];
    float cx = sh.cam[0], cy = sh.cam[1], cz = sh.cam[2];

    float z_low = g_szl[t], z_high = g_szh[t];
    float sdf_low = g_ssl[t], sdf_high = g_ssh[t];
    float denom = SUB(sdf_high, sdf_low);
    float z_pred = ADD(__fdiv_rn(MUL(-sdf_low, SUB(z_high, z_low)),
                                 (denom == 0.f) ? 1.f : denom), z_low);
    for (int i = 0; i < 8; ++i) {
        float sm = sdf_eval(&sh, ADD(cx, MUL(z_pred, dx)), ADD(cy, MUL(z_pred, dy)),
                            ADD(cz, MUL(z_pred, dz)));
        if (sm > 0.f) { z_low = z_pred; sdf_low = sm; }
        if (sm < 0.f) { z_high = z_pred; sdf_high = sm; }
        denom = SUB(sdf_high, sdf_low);
        z_pred = ADD(__fdiv_rn(MUL(-sdf_low, SUB(z_high, z_low)),
                               (denom == 0.f) ? 1.f : denom), z_low);
    }
    out[3 * r + 0] = ADD(cx, MUL(z_pred, dx));
    out[3 * r + 1] = ADD(cy, MUL(z_pred, dy));
    out[3 * r + 2] = ADD(cz, MUL(z_pred, dz));
    out[4 * NRAYS + r] = z_pred;               // out_m already correct (net_surf=1)
}

extern "C" void kernel_launch(void* const* d_in, const int* in_sizes, int n_in,
                              void* d_out, int out_size) {
    const float* cam   = (const float*)d_in[0];
    const void*  omask = d_in[1];
    const float* dirs  = (const float*)d_in[2];
    const float* idl   = (const float*)d_in[3];
    const float* expl  = (const float*)d_in[4];
    const float* W1    = (const float*)d_in[5];
    const float* b1    = (const float*)d_in[6];
    const float* W2    = (const float*)d_in[7];
    const float* b2    = (const float*)d_in[8];
    const float* W3    = (const float*)d_in[9];
    const float* b3    = (const float*)d_in[10];
    float* out = (float*)d_out;

    prep_detect_kernel<<<2, 256>>>(W1, b1, idl, expl, (const unsigned int*)omask);
    trace_init_kernel<<<(2 * NRAYS) / 128, 128>>>(cam, dirs, W1, W2, b2, W3, b3);
    trace_ladder_kernel<<<(2 * NRAYS) / 64, 64>>>(cam, dirs, W1, W2, b2, W3, b3, 1, 3);
    trace_ladder_kernel<<<(2 * NRAYS) / 64, 64>>>(cam, dirs, W1, W2, b2, W3, b3, 3, 5);
    trace_ladder_kernel<<<(2 * NRAYS) / 64, 64>>>(cam, dirs, W1, W2, b2, W3, b3, 5, 7);
    trace_ladder_kernel<<<(2 * NRAYS) / 64, 64>>>(cam, dirs, W1, W2, b2, W3, b3, 7, 9);
    trace_ladder_kernel<<<(2 * NRAYS) / 64, 64>>>(cam, dirs, W1, W2, b2, W3, b3, 9, 10);
    sample_kernel<<<(50 * NRAYS) / 128, 128>>>(cam, dirs, W1, W2, b2, W3, b3);
    finish_a_kernel<<<NRAYS / 256, 256>>>(cam, dirs, omask, out);
    finish_b_kernel<<<NRAYS / 64, 64>>>(cam, dirs, W1, W2, b2, W3, b3, out);
}